// round 4
// baseline (speedup 1.0000x reference)
#include <cuda_runtime.h>
#include <cuda_fp16.h>
#include <cstdint>

#define MAXN 20000
#define MAXE 320000
#define FIN  128
#define HID  64
#define MAXB 8
#define G    8            // nodes per fused-agg block

// ---------------- static device scratch (allocation-free rule) ----------------
__device__ __half g_hw[(size_t)MAXN * MAXB * HID];  // layer-1 transformed feats, node-major
__device__ __half g_h1[(size_t)MAXN * MAXB * HID];  // layer-2 transformed feats (fused out)
__device__ int    g_cnt[MAXN];
__device__ int    g_offs[MAXN + 1];
__device__ int    g_cursor[MAXN];
__device__ float  g_dis[MAXN];
__device__ int    g_csr_src[MAXE];
__device__ float  g_csr_w[MAXE];
__device__ float  g_partial[MAXB * 64];

// ---------------- packed f32x2 helpers ----------------
__device__ __forceinline__ void ffma2(unsigned long long& d, unsigned long long a,
                                      unsigned long long b) {
    asm("fma.rn.f32x2 %0, %1, %2, %0;" : "+l"(d) : "l"(a), "l"(b));
}
__device__ __forceinline__ unsigned long long dup2(float v) {
    unsigned long long r;
    asm("mov.b64 %0, {%1, %1};" : "=l"(r) : "f"(v));
    return r;
}
__device__ __forceinline__ float2 unpk(unsigned long long v) {
    float2 f;
    asm("mov.b64 {%0, %1}, %2;" : "=f"(f.x), "=f"(f.y) : "l"(v));
    return f;
}

// ---------------- HMMA m16n8k16 fp16 -> fp32 ----------------
__device__ __forceinline__ void mma16816(float* c, uint32_t a0, uint32_t a1,
                                         uint32_t a2, uint32_t a3,
                                         uint32_t b0, uint32_t b1) {
    asm volatile(
        "mma.sync.aligned.m16n8k16.row.col.f32.f16.f16.f32 "
        "{%0,%1,%2,%3}, {%4,%5,%6,%7}, {%8,%9}, {%0,%1,%2,%3};"
        : "+f"(c[0]), "+f"(c[1]), "+f"(c[2]), "+f"(c[3])
        : "r"(a0), "r"(a1), "r"(a2), "r"(a3), "r"(b0), "r"(b1));
}

// ---------------- init ----------------
__global__ void k_init(int N) {
    int i = blockIdx.x * blockDim.x + threadIdx.x;
    if (i < N) g_cnt[i] = 0;
    if (i < MAXB * 64) g_partial[i] = 0.0f;
}

// ---------------- in-degree count ----------------
__global__ void k_count(const int* __restrict__ ei, int E) {
    int e = blockIdx.x * blockDim.x + threadIdx.x;
    if (e < E) atomicAdd(&g_cnt[ei[E + e]], 1);
}

// ---------------- single-block scan ----------------
__global__ void k_scan(int N) {
    __shared__ int ss[1024];
    int tid = threadIdx.x;
    int CH = (N + 1023) >> 10;
    int base = tid * CH;
    int s = 0;
    for (int j = 0; j < CH; j++) {
        int i = base + j;
        if (i < N) s += g_cnt[i];
    }
    ss[tid] = s;
    __syncthreads();
    for (int off = 1; off < 1024; off <<= 1) {
        int v = (tid >= off) ? ss[tid - off] : 0;
        __syncthreads();
        ss[tid] += v;
        __syncthreads();
    }
    int run = (tid == 0) ? 0 : ss[tid - 1];
    for (int j = 0; j < CH; j++) {
        int i = base + j;
        if (i < N) {
            g_offs[i] = run;
            g_cursor[i] = run;
            g_dis[i] = rsqrtf(1.0f + (float)g_cnt[i]);
            run += g_cnt[i];
        }
    }
    if (tid == 0) g_offs[N] = ss[1023];
}

// ---------------- CSR fill ----------------
__global__ void k_csr(const int* __restrict__ ei, int E) {
    int e = blockIdx.x * blockDim.x + threadIdx.x;
    if (e < E) {
        int s = ei[e];
        int d = ei[E + e];
        int pos = atomicAdd(&g_cursor[d], 1);
        g_csr_src[pos] = s;
        g_csr_w[pos] = g_dis[s] * g_dis[d];
    }
}

// ---------------- GEMM1 (HMMA): hw = x @ W1, fp32 in -> fp16 out (node-major) ----
#define XS1 136
__global__ void __launch_bounds__(128) k_gemm1(const float* __restrict__ x,
                                               const float* __restrict__ W,
                                               int rows, int N, int B) {
    __shared__ __align__(16) __half Xs[64 * XS1];
    __shared__ __align__(16) __half Wt[64 * XS1];
    int tid = threadIdx.x;
    size_t r0 = (size_t)blockIdx.x * 64;

    for (int idx = tid; idx < FIN * HID; idx += 128) {
        int k = idx >> 6, n = idx & 63;
        Wt[n * XS1 + k] = __float2half_rn(W[idx]);
    }
    for (int idx = tid; idx < 64 * (FIN / 4); idx += 128) {
        int row = idx >> 5, c = idx & 31;
        size_t r = r0 + row;
        float4 v = make_float4(0.f, 0.f, 0.f, 0.f);
        if (r < (size_t)rows) v = *(const float4*)(x + r * FIN + c * 4);
        __half2* p = (__half2*)(Xs + row * XS1 + c * 4);
        p[0] = __floats2half2_rn(v.x, v.y);
        p[1] = __floats2half2_rn(v.z, v.w);
    }
    __syncthreads();

    int wid = tid >> 5, lane = tid & 31;
    int gid = lane >> 2, tig = lane & 3;
    const __half* A0 = Xs + (wid * 16 + gid) * XS1 + 2 * tig;
    const __half* A1 = A0 + 8 * XS1;

    float acc[8][4];
#pragma unroll
    for (int i = 0; i < 8; i++)
#pragma unroll
        for (int j = 0; j < 4; j++) acc[i][j] = 0.f;

#pragma unroll
    for (int ks = 0; ks < FIN / 16; ks++) {
        int k0 = ks * 16;
        uint32_t a0 = *(const uint32_t*)(A0 + k0);
        uint32_t a1 = *(const uint32_t*)(A1 + k0);
        uint32_t a2 = *(const uint32_t*)(A0 + k0 + 8);
        uint32_t a3 = *(const uint32_t*)(A1 + k0 + 8);
#pragma unroll
        for (int nt = 0; nt < 8; nt++) {
            const __half* Bp = Wt + (nt * 8 + gid) * XS1 + k0 + 2 * tig;
            uint32_t b0 = *(const uint32_t*)(Bp);
            uint32_t b1 = *(const uint32_t*)(Bp + 8);
            mma16816(acc[nt], a0, a1, a2, a3, b0, b1);
        }
    }

    size_t r1 = r0 + wid * 16 + gid;
    size_t r2 = r1 + 8;
    if (r1 < (size_t)rows) {
        int n = (int)(r1 % N), b = (int)(r1 / N);
        __half* o = g_hw + ((size_t)n * B + b) * HID + 2 * tig;
#pragma unroll
        for (int nt = 0; nt < 8; nt++)
            *(__half2*)(o + nt * 8) = __floats2half2_rn(acc[nt][0], acc[nt][1]);
    }
    if (r2 < (size_t)rows) {
        int n = (int)(r2 % N), b = (int)(r2 / N);
        __half* o = g_hw + ((size_t)n * B + b) * HID + 2 * tig;
#pragma unroll
        for (int nt = 0; nt < 8; nt++)
            *(__half2*)(o + nt * 8) = __floats2half2_rn(acc[nt][2], acc[nt][3]);
    }
}

// ---------------- fused: agg1 + bias + relu + (h1 @ W2) -> g_h1 (fp16) ----------------
// Block = G nodes. Phase 1: gather-aggregate 8 node rows into smem (L2-bound,
// FMA idle). Phase 2: 64x64x64 transform via packed FFMA2 (overlaps other
// blocks' gathers). Writes layer-2 transformed features to g_h1.
__global__ void __launch_bounds__(256) k_fuse1(const float* __restrict__ bias,
                                               const float* __restrict__ W2,
                                               int N, int Bsz) {
    __shared__ __align__(16) float W2s[64 * 64];   // [k][n] 16KB
    __shared__ __align__(16) float h1s[64][68];    // row = g*B + b
    int tid = threadIdx.x;
    int node0 = blockIdx.x * G;
    int rowlen = Bsz * HID;

    for (int i = tid; i < 64 * 64 / 4; i += 256)
        ((float4*)W2s)[i] = ((const float4*)W2)[i];

    int f = tid * 2;
    if (f < rowlen) {
        int b = f >> 6, h = f & 63;
        float bh0 = bias[h], bh1 = bias[h + 1];
#pragma unroll 1
        for (int g = 0; g < G; g++) {
            int node = node0 + g;
            if (node >= N) break;
            float d = g_dis[node];
            float sn = d * d;
            size_t base = (size_t)node * rowlen + f;
            float2 v = __half22float2(*(const __half2*)(g_hw + base));
            float2 acc = make_float2(fmaf(v.x, sn, bh0), fmaf(v.y, sn, bh1));

            int e = g_offs[node], e1 = g_offs[node + 1];
            for (; e + 1 < e1; e += 2) {
                int s0 = g_csr_src[e];
                int s1 = g_csr_src[e + 1];
                float w0 = g_csr_w[e];
                float w1 = g_csr_w[e + 1];
                float2 m0 = __half22float2(*(const __half2*)(g_hw + (size_t)s0 * rowlen + f));
                float2 m1 = __half22float2(*(const __half2*)(g_hw + (size_t)s1 * rowlen + f));
                acc.x = fmaf(w0, m0.x, acc.x);
                acc.y = fmaf(w0, m0.y, acc.y);
                acc.x = fmaf(w1, m1.x, acc.x);
                acc.y = fmaf(w1, m1.y, acc.y);
            }
            if (e < e1) {
                int s0 = g_csr_src[e];
                float w0 = g_csr_w[e];
                float2 m0 = __half22float2(*(const __half2*)(g_hw + (size_t)s0 * rowlen + f));
                acc.x = fmaf(w0, m0.x, acc.x);
                acc.y = fmaf(w0, m0.y, acc.y);
            }
            int r = g * Bsz + b;
            h1s[r][h] = fmaxf(acc.x, 0.f);
            h1s[r][h + 1] = fmaxf(acc.y, 0.f);
        }
    }
    __syncthreads();

    // phase 2: C[r][n] = sum_k h1s[r][k] * W2s[k][n], r < G*Bsz
    int tx = tid & 15, ty = tid >> 4;   // cols n = tx*4.., rows r = ty*4..
    int rows64 = G * Bsz;
    unsigned long long acc2[4][2];
#pragma unroll
    for (int i = 0; i < 4; i++) { acc2[i][0] = 0ull; acc2[i][1] = 0ull; }

#pragma unroll 4
    for (int k0 = 0; k0 < 64; k0 += 4) {
        ulonglong2 wv[4];
        float4 hv[4];
#pragma unroll
        for (int j = 0; j < 4; j++)
            wv[j] = *(const ulonglong2*)(W2s + (k0 + j) * 64 + tx * 4);
#pragma unroll
        for (int i = 0; i < 4; i++)
            hv[i] = *(const float4*)(&h1s[ty * 4 + i][k0]);
#pragma unroll
        for (int i = 0; i < 4; i++) {
            ffma2(acc2[i][0], dup2(hv[i].x), wv[0].x);
            ffma2(acc2[i][1], dup2(hv[i].x), wv[0].y);
            ffma2(acc2[i][0], dup2(hv[i].y), wv[1].x);
            ffma2(acc2[i][1], dup2(hv[i].y), wv[1].y);
            ffma2(acc2[i][0], dup2(hv[i].z), wv[2].x);
            ffma2(acc2[i][1], dup2(hv[i].z), wv[2].y);
            ffma2(acc2[i][0], dup2(hv[i].w), wv[3].x);
            ffma2(acc2[i][1], dup2(hv[i].w), wv[3].y);
        }
    }

#pragma unroll
    for (int i = 0; i < 4; i++) {
        int r = ty * 4 + i;
        if (r < rows64 && node0 + r / Bsz < N) {
            float2 a0 = unpk(acc2[i][0]);
            float2 a1 = unpk(acc2[i][1]);
            __half2 h0 = __floats2half2_rn(a0.x, a0.y);
            __half2 h1 = __floats2half2_rn(a1.x, a1.y);
            uint2 st;
            st.x = *(unsigned int*)&h0;
            st.y = *(unsigned int*)&h1;
            *(uint2*)(g_h1 + ((size_t)node0 * Bsz + r) * HID + tx * 4) = st;
        }
    }
}

// ---------------- layer-2 aggregation + relu, fused fc dot + mean pool ----------------
__global__ void __launch_bounds__(256) k_agg2(const float* __restrict__ bias,
                                              const float* __restrict__ fcw, int Bsz) {
    int node = blockIdx.x;
    int f = threadIdx.x * 2;
    int rowlen = Bsz * HID;
    if (f >= rowlen) return;
    int h = f & (HID - 1);
    float d = g_dis[node];
    float sn = d * d;
    size_t base = (size_t)node * rowlen;
    float2 v = __half22float2(*(const __half2*)(g_h1 + base + f));
    float2 acc = make_float2(fmaf(v.x, sn, bias[h]), fmaf(v.y, sn, bias[h + 1]));

    int e = g_offs[node], e1 = g_offs[node + 1];
    for (; e + 1 < e1; e += 2) {
        int s0 = g_csr_src[e];
        int s1 = g_csr_src[e + 1];
        float w0 = g_csr_w[e];
        float w1 = g_csr_w[e + 1];
        float2 m0 = __half22float2(*(const __half2*)(g_h1 + (size_t)s0 * rowlen + f));
        float2 m1 = __half22float2(*(const __half2*)(g_h1 + (size_t)s1 * rowlen + f));
        acc.x = fmaf(w0, m0.x, acc.x);
        acc.y = fmaf(w0, m0.y, acc.y);
        acc.x = fmaf(w1, m1.x, acc.x);
        acc.y = fmaf(w1, m1.y, acc.y);
    }
    if (e < e1) {
        int s0 = g_csr_src[e];
        float w0 = g_csr_w[e];
        float2 m0 = __half22float2(*(const __half2*)(g_h1 + (size_t)s0 * rowlen + f));
        acc.x = fmaf(w0, m0.x, acc.x);
        acc.y = fmaf(w0, m0.y, acc.y);
    }
    acc.x = fmaxf(acc.x, 0.f);
    acc.y = fmaxf(acc.y, 0.f);

    float c = acc.x * fcw[h] + acc.y * fcw[h + 1];
#pragma unroll
    for (int o = 16; o; o >>= 1) c += __shfl_xor_sync(0xffffffffu, c, o);
    if ((threadIdx.x & 31) == 0) {
        int b = threadIdx.x >> 5;  // warp == batch
        atomicAdd(&g_partial[b * 64 + (node & 63)], c);
    }
}

// ---------------- final reduce ----------------
__global__ void k_final(float* __restrict__ out, const float* __restrict__ add,
                        const float* __restrict__ fcw, const float* __restrict__ fcb,
                        int N, int Bsz) {
    int b = threadIdx.x >> 5;
    int lane = threadIdx.x & 31;
    if (b < Bsz) {
        float s = g_partial[b * 64 + lane] + g_partial[b * 64 + 32 + lane];
#pragma unroll
        for (int o = 16; o; o >>= 1) s += __shfl_xor_sync(0xffffffffu, s, o);
        if (lane == 0)
            out[b] = s * (1.0f / (float)N) + add[b] * fcw[HID] + fcb[0];
    }
}

// ---------------- launch ----------------
extern "C" void kernel_launch(void* const* d_in, const int* in_sizes, int n_in,
                              void* d_out, int out_size) {
    const float* x   = (const float*)d_in[0];
    const float* add = (const float*)d_in[1];
    const int*   ei  = (const int*)d_in[2];
    const float* W1  = (const float*)d_in[3];
    const float* b1  = (const float*)d_in[4];
    const float* W2  = (const float*)d_in[5];
    const float* b2  = (const float*)d_in[6];
    const float* fcw = (const float*)d_in[7];
    const float* fcb = (const float*)d_in[8];
    float* out = (float*)d_out;

    int B = in_sizes[1];
    int E = in_sizes[2] / 2;
    int N = in_sizes[0] / (B * FIN);
    int rows = B * N;

    // one-time resources for the fork/join capture pattern (created on the
    // non-captured correctness call; reused during capture)
    static cudaStream_t s_side = nullptr;
    static cudaEvent_t ev_fork = nullptr, ev_join = nullptr;
    if (s_side == nullptr) {
        cudaStreamCreateWithFlags(&s_side, cudaStreamNonBlocking);
        cudaEventCreateWithFlags(&ev_fork, cudaEventDisableTiming);
        cudaEventCreateWithFlags(&ev_join, cudaEventDisableTiming);
    }

    k_init<<<(N + 255) / 256, 256>>>(N);

    // fork: graph structure (needs only edge_index) runs beside gemm1
    cudaEventRecord(ev_fork, 0);
    cudaStreamWaitEvent(s_side, ev_fork, 0);
    k_count<<<(E + 255) / 256, 256, 0, s_side>>>(ei, E);
    k_scan<<<1, 1024, 0, s_side>>>(N);
    k_csr<<<(E + 255) / 256, 256, 0, s_side>>>(ei, E);
    cudaEventRecord(ev_join, s_side);

    k_gemm1<<<(rows + 63) / 64, 128>>>(x, W1, rows, N, B);

    // join: fused layer needs both csr and gemm1 output
    cudaStreamWaitEvent(0, ev_join, 0);
    k_fuse1<<<(N + G - 1) / G, 256>>>(b1, W2, N, B);
    k_agg2<<<N, 256>>>(b2, fcw, B);
    k_final<<<1, 256>>>(out, add, fcw, fcb, N, B);
}

// round 5
// speedup vs baseline: 1.1559x; 1.1559x over previous
#include <cuda_runtime.h>
#include <cuda_fp16.h>
#include <cstdint>

#define MAXN 20000
#define MAXE 320000
#define FIN  128
#define HID  64
#define MAXB 8

// ---------------- static device scratch (allocation-free rule) ----------------
__device__ __half g_hw[(size_t)MAXN * MAXB * HID];  // transformed features, node-major [n][b*64]
__device__ __half g_h1[(size_t)MAXN * MAXB * HID];  // layer-1 activations, node-major
__device__ int    g_cnt[MAXN];
__device__ int    g_offs[MAXN + 1];
__device__ int    g_cursor[MAXN];
__device__ float  g_dis[MAXN];
__device__ int    g_csr_src[MAXE];
__device__ float  g_csr_w[MAXE];
__device__ float  g_partial[MAXB * 64];

// ---------------- HMMA m16n8k16 fp16 -> fp32 ----------------
__device__ __forceinline__ void mma16816(float* c, uint32_t a0, uint32_t a1,
                                         uint32_t a2, uint32_t a3,
                                         uint32_t b0, uint32_t b1) {
    asm volatile(
        "mma.sync.aligned.m16n8k16.row.col.f32.f16.f16.f32 "
        "{%0,%1,%2,%3}, {%4,%5,%6,%7}, {%8,%9}, {%0,%1,%2,%3};"
        : "+f"(c[0]), "+f"(c[1]), "+f"(c[2]), "+f"(c[3])
        : "r"(a0), "r"(a1), "r"(a2), "r"(a3), "r"(b0), "r"(b1));
}

// ---------------- init ----------------
__global__ void k_init(int N) {
    int i = blockIdx.x * blockDim.x + threadIdx.x;
    if (i < N) g_cnt[i] = 0;
    if (i < MAXB * 64) g_partial[i] = 0.0f;
}

// ---------------- in-degree count ----------------
__global__ void k_count(const int* __restrict__ ei, int E) {
    int e = blockIdx.x * blockDim.x + threadIdx.x;
    if (e < E) atomicAdd(&g_cnt[ei[E + e]], 1);
}

// ---------------- single-block scan ----------------
__global__ void k_scan(int N) {
    __shared__ int ss[1024];
    int tid = threadIdx.x;
    int CH = (N + 1023) >> 10;
    int base = tid * CH;
    int s = 0;
    for (int j = 0; j < CH; j++) {
        int i = base + j;
        if (i < N) s += g_cnt[i];
    }
    ss[tid] = s;
    __syncthreads();
    for (int off = 1; off < 1024; off <<= 1) {
        int v = (tid >= off) ? ss[tid - off] : 0;
        __syncthreads();
        ss[tid] += v;
        __syncthreads();
    }
    int run = (tid == 0) ? 0 : ss[tid - 1];
    for (int j = 0; j < CH; j++) {
        int i = base + j;
        if (i < N) {
            g_offs[i] = run;
            g_cursor[i] = run;
            g_dis[i] = rsqrtf(1.0f + (float)g_cnt[i]);
            run += g_cnt[i];
        }
    }
    if (tid == 0) g_offs[N] = ss[1023];
}

// ---------------- CSR fill ----------------
__global__ void k_csr(const int* __restrict__ ei, int E) {
    int e = blockIdx.x * blockDim.x + threadIdx.x;
    if (e < E) {
        int s = ei[e];
        int d = ei[E + e];
        int pos = atomicAdd(&g_cursor[d], 1);
        g_csr_src[pos] = s;
        g_csr_w[pos] = g_dis[s] * g_dis[d];
    }
}

// ---------------- GEMM1 (HMMA): hw = x @ W1, fp32 in -> fp16 out (node-major) ----
#define XS1 136
__global__ void __launch_bounds__(128) k_gemm1(const float* __restrict__ x,
                                               const float* __restrict__ W,
                                               int rows, int N, int B) {
    __shared__ __align__(16) __half Xs[64 * XS1];
    __shared__ __align__(16) __half Wt[64 * XS1];
    int tid = threadIdx.x;
    size_t r0 = (size_t)blockIdx.x * 64;

    for (int idx = tid; idx < FIN * HID; idx += 128) {
        int k = idx >> 6, n = idx & 63;
        Wt[n * XS1 + k] = __float2half_rn(W[idx]);
    }
    for (int idx = tid; idx < 64 * (FIN / 4); idx += 128) {
        int row = idx >> 5, c = idx & 31;
        size_t r = r0 + row;
        float4 v = make_float4(0.f, 0.f, 0.f, 0.f);
        if (r < (size_t)rows) v = *(const float4*)(x + r * FIN + c * 4);
        __half2* p = (__half2*)(Xs + row * XS1 + c * 4);
        p[0] = __floats2half2_rn(v.x, v.y);
        p[1] = __floats2half2_rn(v.z, v.w);
    }
    __syncthreads();

    int wid = tid >> 5, lane = tid & 31;
    int gid = lane >> 2, tig = lane & 3;
    const __half* A0 = Xs + (wid * 16 + gid) * XS1 + 2 * tig;
    const __half* A1 = A0 + 8 * XS1;

    float acc[8][4];
#pragma unroll
    for (int i = 0; i < 8; i++)
#pragma unroll
        for (int j = 0; j < 4; j++) acc[i][j] = 0.f;

#pragma unroll
    for (int ks = 0; ks < FIN / 16; ks++) {
        int k0 = ks * 16;
        uint32_t a0 = *(const uint32_t*)(A0 + k0);
        uint32_t a1 = *(const uint32_t*)(A1 + k0);
        uint32_t a2 = *(const uint32_t*)(A0 + k0 + 8);
        uint32_t a3 = *(const uint32_t*)(A1 + k0 + 8);
#pragma unroll
        for (int nt = 0; nt < 8; nt++) {
            const __half* Bp = Wt + (nt * 8 + gid) * XS1 + k0 + 2 * tig;
            uint32_t b0 = *(const uint32_t*)(Bp);
            uint32_t b1 = *(const uint32_t*)(Bp + 8);
            mma16816(acc[nt], a0, a1, a2, a3, b0, b1);
        }
    }

    size_t r1 = r0 + wid * 16 + gid;
    size_t r2 = r1 + 8;
    if (r1 < (size_t)rows) {
        int n = (int)(r1 % N), b = (int)(r1 / N);
        __half* o = g_hw + ((size_t)n * B + b) * HID + 2 * tig;
#pragma unroll
        for (int nt = 0; nt < 8; nt++)
            *(__half2*)(o + nt * 8) = __floats2half2_rn(acc[nt][0], acc[nt][1]);
    }
    if (r2 < (size_t)rows) {
        int n = (int)(r2 % N), b = (int)(r2 / N);
        __half* o = g_hw + ((size_t)n * B + b) * HID + 2 * tig;
#pragma unroll
        for (int nt = 0; nt < 8; nt++)
            *(__half2*)(o + nt * 8) = __floats2half2_rn(acc[nt][2], acc[nt][3]);
    }
}

// ---------------- GEMM2 (HMMA): hw = h1 @ W2, fp16 in (node-major) -> fp16 out ----
#define XS2 72
__global__ void __launch_bounds__(128) k_gemm2(const float* __restrict__ W, int rows) {
    __shared__ __align__(16) __half Xs[64 * XS2];
    __shared__ __align__(16) __half Wt[64 * XS2];
    int tid = threadIdx.x;
    size_t r0 = (size_t)blockIdx.x * 64;

    for (int idx = tid; idx < HID * HID; idx += 128) {
        int k = idx >> 6, n = idx & 63;
        Wt[n * XS2 + k] = __float2half_rn(W[idx]);
    }
    for (int idx = tid; idx < 64 * (HID / 8); idx += 128) {
        int row = idx >> 3, c = idx & 7;
        size_t r = r0 + row;
        uint4 v = make_uint4(0u, 0u, 0u, 0u);
        if (r < (size_t)rows) v = *(const uint4*)(g_h1 + r * HID + c * 8);
        *(uint4*)(Xs + row * XS2 + c * 8) = v;
    }
    __syncthreads();

    int wid = tid >> 5, lane = tid & 31;
    int gid = lane >> 2, tig = lane & 3;
    const __half* A0 = Xs + (wid * 16 + gid) * XS2 + 2 * tig;
    const __half* A1 = A0 + 8 * XS2;

    float acc[8][4];
#pragma unroll
    for (int i = 0; i < 8; i++)
#pragma unroll
        for (int j = 0; j < 4; j++) acc[i][j] = 0.f;

#pragma unroll
    for (int ks = 0; ks < HID / 16; ks++) {
        int k0 = ks * 16;
        uint32_t a0 = *(const uint32_t*)(A0 + k0);
        uint32_t a1 = *(const uint32_t*)(A1 + k0);
        uint32_t a2 = *(const uint32_t*)(A0 + k0 + 8);
        uint32_t a3 = *(const uint32_t*)(A1 + k0 + 8);
#pragma unroll
        for (int nt = 0; nt < 8; nt++) {
            const __half* Bp = Wt + (nt * 8 + gid) * XS2 + k0 + 2 * tig;
            uint32_t b0 = *(const uint32_t*)(Bp);
            uint32_t b1 = *(const uint32_t*)(Bp + 8);
            mma16816(acc[nt], a0, a1, a2, a3, b0, b1);
        }
    }

    size_t r1 = r0 + wid * 16 + gid;
    size_t r2 = r1 + 8;
    if (r1 < (size_t)rows) {
        __half* o = g_hw + r1 * HID + 2 * tig;
#pragma unroll
        for (int nt = 0; nt < 8; nt++)
            *(__half2*)(o + nt * 8) = __floats2half2_rn(acc[nt][0], acc[nt][1]);
    }
    if (r2 < (size_t)rows) {
        __half* o = g_hw + r2 * HID + 2 * tig;
#pragma unroll
        for (int nt = 0; nt < 8; nt++)
            *(__half2*)(o + nt * 8) = __floats2half2_rn(acc[nt][2], acc[nt][3]);
    }
}

// ---------------- layer-1 aggregation + bias + relu -> g_h1 (fp16) ----------------
// One block per dst node; edge loop unrolled x4 for gather MLP.
__global__ void __launch_bounds__(256) k_agg1(const float* __restrict__ bias, int Bsz) {
    int node = blockIdx.x;
    int f = threadIdx.x * 2;
    int rowlen = Bsz * HID;
    if (f >= rowlen) return;
    int h = f & (HID - 1);
    float d = g_dis[node];
    float sn = d * d;
    size_t base = (size_t)node * rowlen;
    float2 v = __half22float2(*(const __half2*)(g_hw + base + f));
    float2 acc = make_float2(fmaf(v.x, sn, bias[h]), fmaf(v.y, sn, bias[h + 1]));

    int e = g_offs[node], e1 = g_offs[node + 1];
    for (; e + 3 < e1; e += 4) {
        int s0 = g_csr_src[e], s1 = g_csr_src[e + 1];
        int s2 = g_csr_src[e + 2], s3 = g_csr_src[e + 3];
        float w0 = g_csr_w[e], w1 = g_csr_w[e + 1];
        float w2 = g_csr_w[e + 2], w3 = g_csr_w[e + 3];
        float2 m0 = __half22float2(*(const __half2*)(g_hw + (size_t)s0 * rowlen + f));
        float2 m1 = __half22float2(*(const __half2*)(g_hw + (size_t)s1 * rowlen + f));
        float2 m2 = __half22float2(*(const __half2*)(g_hw + (size_t)s2 * rowlen + f));
        float2 m3 = __half22float2(*(const __half2*)(g_hw + (size_t)s3 * rowlen + f));
        acc.x = fmaf(w0, m0.x, acc.x); acc.y = fmaf(w0, m0.y, acc.y);
        acc.x = fmaf(w1, m1.x, acc.x); acc.y = fmaf(w1, m1.y, acc.y);
        acc.x = fmaf(w2, m2.x, acc.x); acc.y = fmaf(w2, m2.y, acc.y);
        acc.x = fmaf(w3, m3.x, acc.x); acc.y = fmaf(w3, m3.y, acc.y);
    }
    for (; e < e1; e++) {
        int s0 = g_csr_src[e];
        float w0 = g_csr_w[e];
        float2 m0 = __half22float2(*(const __half2*)(g_hw + (size_t)s0 * rowlen + f));
        acc.x = fmaf(w0, m0.x, acc.x);
        acc.y = fmaf(w0, m0.y, acc.y);
    }
    acc.x = fmaxf(acc.x, 0.f);
    acc.y = fmaxf(acc.y, 0.f);
    *(__half2*)(g_h1 + base + f) = __floats2half2_rn(acc.x, acc.y);
}

// ---------------- layer-2 aggregation + relu, fused fc dot + mean pool ----------------
__global__ void __launch_bounds__(256) k_agg2(const float* __restrict__ bias,
                                              const float* __restrict__ fcw, int Bsz) {
    int node = blockIdx.x;
    int f = threadIdx.x * 2;
    int rowlen = Bsz * HID;
    if (f >= rowlen) return;
    int h = f & (HID - 1);
    float d = g_dis[node];
    float sn = d * d;
    size_t base = (size_t)node * rowlen;
    float2 v = __half22float2(*(const __half2*)(g_hw + base + f));
    float2 acc = make_float2(fmaf(v.x, sn, bias[h]), fmaf(v.y, sn, bias[h + 1]));

    int e = g_offs[node], e1 = g_offs[node + 1];
    for (; e + 3 < e1; e += 4) {
        int s0 = g_csr_src[e], s1 = g_csr_src[e + 1];
        int s2 = g_csr_src[e + 2], s3 = g_csr_src[e + 3];
        float w0 = g_csr_w[e], w1 = g_csr_w[e + 1];
        float w2 = g_csr_w[e + 2], w3 = g_csr_w[e + 3];
        float2 m0 = __half22float2(*(const __half2*)(g_hw + (size_t)s0 * rowlen + f));
        float2 m1 = __half22float2(*(const __half2*)(g_hw + (size_t)s1 * rowlen + f));
        float2 m2 = __half22float2(*(const __half2*)(g_hw + (size_t)s2 * rowlen + f));
        float2 m3 = __half22float2(*(const __half2*)(g_hw + (size_t)s3 * rowlen + f));
        acc.x = fmaf(w0, m0.x, acc.x); acc.y = fmaf(w0, m0.y, acc.y);
        acc.x = fmaf(w1, m1.x, acc.x); acc.y = fmaf(w1, m1.y, acc.y);
        acc.x = fmaf(w2, m2.x, acc.x); acc.y = fmaf(w2, m2.y, acc.y);
        acc.x = fmaf(w3, m3.x, acc.x); acc.y = fmaf(w3, m3.y, acc.y);
    }
    for (; e < e1; e++) {
        int s0 = g_csr_src[e];
        float w0 = g_csr_w[e];
        float2 m0 = __half22float2(*(const __half2*)(g_hw + (size_t)s0 * rowlen + f));
        acc.x = fmaf(w0, m0.x, acc.x);
        acc.y = fmaf(w0, m0.y, acc.y);
    }
    acc.x = fmaxf(acc.x, 0.f);
    acc.y = fmaxf(acc.y, 0.f);

    float c = acc.x * fcw[h] + acc.y * fcw[h + 1];
#pragma unroll
    for (int o = 16; o; o >>= 1) c += __shfl_xor_sync(0xffffffffu, c, o);
    if ((threadIdx.x & 31) == 0) {
        int b = threadIdx.x >> 5;  // warp == batch
        atomicAdd(&g_partial[b * 64 + (node & 63)], c);
    }
}

// ---------------- final reduce ----------------
__global__ void k_final(float* __restrict__ out, const float* __restrict__ add,
                        const float* __restrict__ fcw, const float* __restrict__ fcb,
                        int N, int Bsz) {
    int b = threadIdx.x >> 5;
    int lane = threadIdx.x & 31;
    if (b < Bsz) {
        float s = g_partial[b * 64 + lane] + g_partial[b * 64 + 32 + lane];
#pragma unroll
        for (int o = 16; o; o >>= 1) s += __shfl_xor_sync(0xffffffffu, s, o);
        if (lane == 0)
            out[b] = s * (1.0f / (float)N) + add[b] * fcw[HID] + fcb[0];
    }
}

// ---------------- launch ----------------
extern "C" void kernel_launch(void* const* d_in, const int* in_sizes, int n_in,
                              void* d_out, int out_size) {
    const float* x   = (const float*)d_in[0];
    const float* add = (const float*)d_in[1];
    const int*   ei  = (const int*)d_in[2];
    const float* W1  = (const float*)d_in[3];
    const float* b1  = (const float*)d_in[4];
    const float* W2  = (const float*)d_in[5];
    const float* b2  = (const float*)d_in[6];
    const float* fcw = (const float*)d_in[7];
    const float* fcb = (const float*)d_in[8];
    float* out = (float*)d_out;

    int B = in_sizes[1];
    int E = in_sizes[2] / 2;
    int N = in_sizes[0] / (B * FIN);
    int rows = B * N;

    static cudaStream_t s_side = nullptr;
    static cudaEvent_t ev_fork = nullptr, ev_join = nullptr;
    if (s_side == nullptr) {
        cudaStreamCreateWithFlags(&s_side, cudaStreamNonBlocking);
        cudaEventCreateWithFlags(&ev_fork, cudaEventDisableTiming);
        cudaEventCreateWithFlags(&ev_join, cudaEventDisableTiming);
    }

    k_init<<<(N + 255) / 256, 256>>>(N);

    // fork: graph structure (needs only edge_index) runs beside gemm1
    cudaEventRecord(ev_fork, 0);
    cudaStreamWaitEvent(s_side, ev_fork, 0);
    k_count<<<(E + 255) / 256, 256, 0, s_side>>>(ei, E);
    k_scan<<<1, 1024, 0, s_side>>>(N);
    k_csr<<<(E + 255) / 256, 256, 0, s_side>>>(ei, E);
    cudaEventRecord(ev_join, s_side);

    k_gemm1<<<(rows + 63) / 64, 128>>>(x, W1, rows, N, B);

    // join: agg1 needs both csr and gemm1 output
    cudaStreamWaitEvent(0, ev_join, 0);
    k_agg1<<<N, 256>>>(b1, B);
    k_gemm2<<<(rows + 63) / 64, 128>>>(W2, rows);
    k_agg2<<<N, 256>>>(b2, fcw, B);
    k_final<<<1, 256>>>(out, add, fcw, fcb, N, B);
}

// round 6
// speedup vs baseline: 1.3863x; 1.1993x over previous
#include <cuda_runtime.h>
#include <cuda_fp16.h>
#include <cuda_fp8.h>
#include <cstdint>

#define MAXN 20000
#define MAXE 320000
#define FIN  128
#define HID  64
#define MAXB 8

// ---------------- static device scratch (allocation-free rule) ----------------
__device__ unsigned char g_f8[(size_t)MAXN * MAXB * HID];  // fp8 e4m3 gather buffer (layer1 feats, then layer2 feats)
__device__ __half g_h1[(size_t)MAXN * MAXB * HID];         // layer-1 activations (fp16, feeds gemm2)
__device__ int    g_cnt[MAXN];
__device__ int    g_offs[MAXN + 1];
__device__ int    g_cursor[MAXN];
__device__ float  g_dis[MAXN];
__device__ int    g_csr_src[MAXE];
__device__ float  g_csr_w[MAXE];
__device__ float  g_partial[MAXB * 64];

// ---------------- fp8 helpers ----------------
__device__ __forceinline__ float4 f8x4_to_f4(uint32_t p) {
    __half2_raw lo = __nv_cvt_fp8x2_to_halfraw2((__nv_fp8x2_storage_t)(p & 0xffffu), __NV_E4M3);
    __half2_raw hi = __nv_cvt_fp8x2_to_halfraw2((__nv_fp8x2_storage_t)(p >> 16), __NV_E4M3);
    float2 a = __half22float2(*(__half2*)&lo);
    float2 b = __half22float2(*(__half2*)&hi);
    return make_float4(a.x, a.y, b.x, b.y);
}
__device__ __forceinline__ unsigned short f2_to_f8x2(float a, float b) {
    return (unsigned short)__nv_cvt_float2_to_fp8x2(make_float2(a, b), __NV_SATFINITE, __NV_E4M3);
}

// ---------------- HMMA m16n8k16 fp16 -> fp32 ----------------
__device__ __forceinline__ void mma16816(float* c, uint32_t a0, uint32_t a1,
                                         uint32_t a2, uint32_t a3,
                                         uint32_t b0, uint32_t b1) {
    asm volatile(
        "mma.sync.aligned.m16n8k16.row.col.f32.f16.f16.f32 "
        "{%0,%1,%2,%3}, {%4,%5,%6,%7}, {%8,%9}, {%0,%1,%2,%3};"
        : "+f"(c[0]), "+f"(c[1]), "+f"(c[2]), "+f"(c[3])
        : "r"(a0), "r"(a1), "r"(a2), "r"(a3), "r"(b0), "r"(b1));
}

// ---------------- init ----------------
__global__ void k_init(int N) {
    int i = blockIdx.x * blockDim.x + threadIdx.x;
    if (i < N) g_cnt[i] = 0;
    if (i < MAXB * 64) g_partial[i] = 0.0f;
}

// ---------------- in-degree count ----------------
__global__ void k_count(const int* __restrict__ ei, int E) {
    int e = blockIdx.x * blockDim.x + threadIdx.x;
    if (e < E) atomicAdd(&g_cnt[ei[E + e]], 1);
}

// ---------------- single-block scan ----------------
__global__ void k_scan(int N) {
    __shared__ int ss[1024];
    int tid = threadIdx.x;
    int CH = (N + 1023) >> 10;
    int base = tid * CH;
    int s = 0;
    for (int j = 0; j < CH; j++) {
        int i = base + j;
        if (i < N) s += g_cnt[i];
    }
    ss[tid] = s;
    __syncthreads();
    for (int off = 1; off < 1024; off <<= 1) {
        int v = (tid >= off) ? ss[tid - off] : 0;
        __syncthreads();
        ss[tid] += v;
        __syncthreads();
    }
    int run = (tid == 0) ? 0 : ss[tid - 1];
    for (int j = 0; j < CH; j++) {
        int i = base + j;
        if (i < N) {
            g_offs[i] = run;
            g_cursor[i] = run;
            g_dis[i] = rsqrtf(1.0f + (float)g_cnt[i]);
            run += g_cnt[i];
        }
    }
    if (tid == 0) g_offs[N] = ss[1023];
}

// ---------------- CSR fill ----------------
__global__ void k_csr(const int* __restrict__ ei, int E) {
    int e = blockIdx.x * blockDim.x + threadIdx.x;
    if (e < E) {
        int s = ei[e];
        int d = ei[E + e];
        int pos = atomicAdd(&g_cursor[d], 1);
        g_csr_src[pos] = s;
        g_csr_w[pos] = g_dis[s] * g_dis[d];
    }
}

// ---------------- GEMM1 (HMMA): f8 = x @ W1, fp32 in -> fp8 out (node-major) ----
#define XS1 136
__global__ void __launch_bounds__(128) k_gemm1(const float* __restrict__ x,
                                               const float* __restrict__ W,
                                               int rows, int N, int B) {
    __shared__ __align__(16) __half Xs[64 * XS1];
    __shared__ __align__(16) __half Wt[64 * XS1];
    int tid = threadIdx.x;
    size_t r0 = (size_t)blockIdx.x * 64;

    for (int idx = tid; idx < FIN * HID; idx += 128) {
        int k = idx >> 6, n = idx & 63;
        Wt[n * XS1 + k] = __float2half_rn(W[idx]);
    }
    for (int idx = tid; idx < 64 * (FIN / 4); idx += 128) {
        int row = idx >> 5, c = idx & 31;
        size_t r = r0 + row;
        float4 v = make_float4(0.f, 0.f, 0.f, 0.f);
        if (r < (size_t)rows) v = *(const float4*)(x + r * FIN + c * 4);
        __half2* p = (__half2*)(Xs + row * XS1 + c * 4);
        p[0] = __floats2half2_rn(v.x, v.y);
        p[1] = __floats2half2_rn(v.z, v.w);
    }
    __syncthreads();

    int wid = tid >> 5, lane = tid & 31;
    int gid = lane >> 2, tig = lane & 3;
    const __half* A0 = Xs + (wid * 16 + gid) * XS1 + 2 * tig;
    const __half* A1 = A0 + 8 * XS1;

    float acc[8][4];
#pragma unroll
    for (int i = 0; i < 8; i++)
#pragma unroll
        for (int j = 0; j < 4; j++) acc[i][j] = 0.f;

#pragma unroll
    for (int ks = 0; ks < FIN / 16; ks++) {
        int k0 = ks * 16;
        uint32_t a0 = *(const uint32_t*)(A0 + k0);
        uint32_t a1 = *(const uint32_t*)(A1 + k0);
        uint32_t a2 = *(const uint32_t*)(A0 + k0 + 8);
        uint32_t a3 = *(const uint32_t*)(A1 + k0 + 8);
#pragma unroll
        for (int nt = 0; nt < 8; nt++) {
            const __half* Bp = Wt + (nt * 8 + gid) * XS1 + k0 + 2 * tig;
            uint32_t b0 = *(const uint32_t*)(Bp);
            uint32_t b1 = *(const uint32_t*)(Bp + 8);
            mma16816(acc[nt], a0, a1, a2, a3, b0, b1);
        }
    }

    size_t r1 = r0 + wid * 16 + gid;
    size_t r2 = r1 + 8;
    if (r1 < (size_t)rows) {
        int n = (int)(r1 % N), b = (int)(r1 / N);
        unsigned char* o = g_f8 + ((size_t)n * B + b) * HID + 2 * tig;
#pragma unroll
        for (int nt = 0; nt < 8; nt++)
            *(unsigned short*)(o + nt * 8) = f2_to_f8x2(acc[nt][0], acc[nt][1]);
    }
    if (r2 < (size_t)rows) {
        int n = (int)(r2 % N), b = (int)(r2 / N);
        unsigned char* o = g_f8 + ((size_t)n * B + b) * HID + 2 * tig;
#pragma unroll
        for (int nt = 0; nt < 8; nt++)
            *(unsigned short*)(o + nt * 8) = f2_to_f8x2(acc[nt][2], acc[nt][3]);
    }
}

// ---------------- GEMM2 (HMMA): f8 = h1 @ W2, fp16 in (node-major) -> fp8 out ----
#define XS2 72
__global__ void __launch_bounds__(128) k_gemm2(const float* __restrict__ W, int rows) {
    __shared__ __align__(16) __half Xs[64 * XS2];
    __shared__ __align__(16) __half Wt[64 * XS2];
    int tid = threadIdx.x;
    size_t r0 = (size_t)blockIdx.x * 64;

    for (int idx = tid; idx < HID * HID; idx += 128) {
        int k = idx >> 6, n = idx & 63;
        Wt[n * XS2 + k] = __float2half_rn(W[idx]);
    }
    for (int idx = tid; idx < 64 * (HID / 8); idx += 128) {
        int row = idx >> 3, c = idx & 7;
        size_t r = r0 + row;
        uint4 v = make_uint4(0u, 0u, 0u, 0u);
        if (r < (size_t)rows) v = *(const uint4*)(g_h1 + r * HID + c * 8);
        *(uint4*)(Xs + row * XS2 + c * 8) = v;
    }
    __syncthreads();

    int wid = tid >> 5, lane = tid & 31;
    int gid = lane >> 2, tig = lane & 3;
    const __half* A0 = Xs + (wid * 16 + gid) * XS2 + 2 * tig;
    const __half* A1 = A0 + 8 * XS2;

    float acc[8][4];
#pragma unroll
    for (int i = 0; i < 8; i++)
#pragma unroll
        for (int j = 0; j < 4; j++) acc[i][j] = 0.f;

#pragma unroll
    for (int ks = 0; ks < HID / 16; ks++) {
        int k0 = ks * 16;
        uint32_t a0 = *(const uint32_t*)(A0 + k0);
        uint32_t a1 = *(const uint32_t*)(A1 + k0);
        uint32_t a2 = *(const uint32_t*)(A0 + k0 + 8);
        uint32_t a3 = *(const uint32_t*)(A1 + k0 + 8);
#pragma unroll
        for (int nt = 0; nt < 8; nt++) {
            const __half* Bp = Wt + (nt * 8 + gid) * XS2 + k0 + 2 * tig;
            uint32_t b0 = *(const uint32_t*)(Bp);
            uint32_t b1 = *(const uint32_t*)(Bp + 8);
            mma16816(acc[nt], a0, a1, a2, a3, b0, b1);
        }
    }

    size_t r1 = r0 + wid * 16 + gid;
    size_t r2 = r1 + 8;
    if (r1 < (size_t)rows) {
        unsigned char* o = g_f8 + r1 * HID + 2 * tig;
#pragma unroll
        for (int nt = 0; nt < 8; nt++)
            *(unsigned short*)(o + nt * 8) = f2_to_f8x2(acc[nt][0], acc[nt][1]);
    }
    if (r2 < (size_t)rows) {
        unsigned char* o = g_f8 + r2 * HID + 2 * tig;
#pragma unroll
        for (int nt = 0; nt < 8; nt++)
            *(unsigned short*)(o + nt * 8) = f2_to_f8x2(acc[nt][2], acc[nt][3]);
    }
}

// ---------------- layer-1 aggregation + bias + relu -> g_h1 (fp16) ----------------
// 2 nodes per block; 128 threads per node, 4 features/thread (fp8x4 gathers).
__global__ void __launch_bounds__(256) k_agg1(const float* __restrict__ bias,
                                              int N, int Bsz) {
    int lt = threadIdx.x & 127;
    int node = blockIdx.x * 2 + (threadIdx.x >> 7);
    if (node >= N) return;
    int f = lt * 4;
    int rowlen = Bsz * HID;
    if (f >= rowlen) return;
    int h = f & (HID - 1);
    float d = g_dis[node];
    float sn = d * d;
    size_t base = (size_t)node * rowlen;

    float4 bz = make_float4(bias[h], bias[h + 1], bias[h + 2], bias[h + 3]);
    float4 v = f8x4_to_f4(*(const uint32_t*)(g_f8 + base + f));
    float4 acc = make_float4(fmaf(v.x, sn, bz.x), fmaf(v.y, sn, bz.y),
                             fmaf(v.z, sn, bz.z), fmaf(v.w, sn, bz.w));

    int e = g_offs[node], e1 = g_offs[node + 1];
    for (; e + 3 < e1; e += 4) {
        int s0 = g_csr_src[e], s1 = g_csr_src[e + 1];
        int s2 = g_csr_src[e + 2], s3 = g_csr_src[e + 3];
        float w0 = g_csr_w[e], w1 = g_csr_w[e + 1];
        float w2 = g_csr_w[e + 2], w3 = g_csr_w[e + 3];
        float4 m0 = f8x4_to_f4(*(const uint32_t*)(g_f8 + (size_t)s0 * rowlen + f));
        float4 m1 = f8x4_to_f4(*(const uint32_t*)(g_f8 + (size_t)s1 * rowlen + f));
        float4 m2 = f8x4_to_f4(*(const uint32_t*)(g_f8 + (size_t)s2 * rowlen + f));
        float4 m3 = f8x4_to_f4(*(const uint32_t*)(g_f8 + (size_t)s3 * rowlen + f));
        acc.x = fmaf(w0, m0.x, acc.x); acc.y = fmaf(w0, m0.y, acc.y);
        acc.z = fmaf(w0, m0.z, acc.z); acc.w = fmaf(w0, m0.w, acc.w);
        acc.x = fmaf(w1, m1.x, acc.x); acc.y = fmaf(w1, m1.y, acc.y);
        acc.z = fmaf(w1, m1.z, acc.z); acc.w = fmaf(w1, m1.w, acc.w);
        acc.x = fmaf(w2, m2.x, acc.x); acc.y = fmaf(w2, m2.y, acc.y);
        acc.z = fmaf(w2, m2.z, acc.z); acc.w = fmaf(w2, m2.w, acc.w);
        acc.x = fmaf(w3, m3.x, acc.x); acc.y = fmaf(w3, m3.y, acc.y);
        acc.z = fmaf(w3, m3.z, acc.z); acc.w = fmaf(w3, m3.w, acc.w);
    }
    for (; e < e1; e++) {
        int s0 = g_csr_src[e];
        float w0 = g_csr_w[e];
        float4 m0 = f8x4_to_f4(*(const uint32_t*)(g_f8 + (size_t)s0 * rowlen + f));
        acc.x = fmaf(w0, m0.x, acc.x); acc.y = fmaf(w0, m0.y, acc.y);
        acc.z = fmaf(w0, m0.z, acc.z); acc.w = fmaf(w0, m0.w, acc.w);
    }
    __half2 o0 = __floats2half2_rn(fmaxf(acc.x, 0.f), fmaxf(acc.y, 0.f));
    __half2 o1 = __floats2half2_rn(fmaxf(acc.z, 0.f), fmaxf(acc.w, 0.f));
    uint2 st;
    st.x = *(unsigned int*)&o0;
    st.y = *(unsigned int*)&o1;
    *(uint2*)(g_h1 + base + f) = st;
}

// ---------------- layer-2 aggregation + relu, fused fc dot + mean pool ----------------
__global__ void __launch_bounds__(256) k_agg2(const float* __restrict__ bias,
                                              const float* __restrict__ fcw,
                                              int N, int Bsz) {
    int lt = threadIdx.x & 127;
    int node = blockIdx.x * 2 + (threadIdx.x >> 7);
    if (node >= N) return;
    int f = lt * 4;
    int rowlen = Bsz * HID;
    if (f >= rowlen) return;
    int h = f & (HID - 1);
    float d = g_dis[node];
    float sn = d * d;
    size_t base = (size_t)node * rowlen;

    float4 bz = make_float4(bias[h], bias[h + 1], bias[h + 2], bias[h + 3]);
    float4 v = f8x4_to_f4(*(const uint32_t*)(g_f8 + base + f));
    float4 acc = make_float4(fmaf(v.x, sn, bz.x), fmaf(v.y, sn, bz.y),
                             fmaf(v.z, sn, bz.z), fmaf(v.w, sn, bz.w));

    int e = g_offs[node], e1 = g_offs[node + 1];
    for (; e + 3 < e1; e += 4) {
        int s0 = g_csr_src[e], s1 = g_csr_src[e + 1];
        int s2 = g_csr_src[e + 2], s3 = g_csr_src[e + 3];
        float w0 = g_csr_w[e], w1 = g_csr_w[e + 1];
        float w2 = g_csr_w[e + 2], w3 = g_csr_w[e + 3];
        float4 m0 = f8x4_to_f4(*(const uint32_t*)(g_f8 + (size_t)s0 * rowlen + f));
        float4 m1 = f8x4_to_f4(*(const uint32_t*)(g_f8 + (size_t)s1 * rowlen + f));
        float4 m2 = f8x4_to_f4(*(const uint32_t*)(g_f8 + (size_t)s2 * rowlen + f));
        float4 m3 = f8x4_to_f4(*(const uint32_t*)(g_f8 + (size_t)s3 * rowlen + f));
        acc.x = fmaf(w0, m0.x, acc.x); acc.y = fmaf(w0, m0.y, acc.y);
        acc.z = fmaf(w0, m0.z, acc.z); acc.w = fmaf(w0, m0.w, acc.w);
        acc.x = fmaf(w1, m1.x, acc.x); acc.y = fmaf(w1, m1.y, acc.y);
        acc.z = fmaf(w1, m1.z, acc.z); acc.w = fmaf(w1, m1.w, acc.w);
        acc.x = fmaf(w2, m2.x, acc.x); acc.y = fmaf(w2, m2.y, acc.y);
        acc.z = fmaf(w2, m2.z, acc.z); acc.w = fmaf(w2, m2.w, acc.w);
        acc.x = fmaf(w3, m3.x, acc.x); acc.y = fmaf(w3, m3.y, acc.y);
        acc.z = fmaf(w3, m3.z, acc.z); acc.w = fmaf(w3, m3.w, acc.w);
    }
    for (; e < e1; e++) {
        int s0 = g_csr_src[e];
        float w0 = g_csr_w[e];
        float4 m0 = f8x4_to_f4(*(const uint32_t*)(g_f8 + (size_t)s0 * rowlen + f));
        acc.x = fmaf(w0, m0.x, acc.x); acc.y = fmaf(w0, m0.y, acc.y);
        acc.z = fmaf(w0, m0.z, acc.z); acc.w = fmaf(w0, m0.w, acc.w);
    }

    float c = fmaxf(acc.x, 0.f) * fcw[h] + fmaxf(acc.y, 0.f) * fcw[h + 1] +
              fmaxf(acc.z, 0.f) * fcw[h + 2] + fmaxf(acc.w, 0.f) * fcw[h + 3];
    // reduce within 16-lane groups (one batch per group: lt 0-15 -> b0, etc.)
#pragma unroll
    for (int o = 8; o; o >>= 1) c += __shfl_xor_sync(0xffffffffu, c, o);
    if ((threadIdx.x & 15) == 0) {
        int b = lt >> 4;
        atomicAdd(&g_partial[b * 64 + (node & 63)], c);
    }
}

// ---------------- final reduce ----------------
__global__ void k_final(float* __restrict__ out, const float* __restrict__ add,
                        const float* __restrict__ fcw, const float* __restrict__ fcb,
                        int N, int Bsz) {
    int b = threadIdx.x >> 5;
    int lane = threadIdx.x & 31;
    if (b < Bsz) {
        float s = g_partial[b * 64 + lane] + g_partial[b * 64 + 32 + lane];
#pragma unroll
        for (int o = 16; o; o >>= 1) s += __shfl_xor_sync(0xffffffffu, s, o);
        if (lane == 0)
            out[b] = s * (1.0f / (float)N) + add[b] * fcw[HID] + fcb[0];
    }
}

// ---------------- launch ----------------
extern "C" void kernel_launch(void* const* d_in, const int* in_sizes, int n_in,
                              void* d_out, int out_size) {
    const float* x   = (const float*)d_in[0];
    const float* add = (const float*)d_in[1];
    const int*   ei  = (const int*)d_in[2];
    const float* W1  = (const float*)d_in[3];
    const float* b1  = (const float*)d_in[4];
    const float* W2  = (const float*)d_in[5];
    const float* b2  = (const float*)d_in[6];
    const float* fcw = (const float*)d_in[7];
    const float* fcb = (const float*)d_in[8];
    float* out = (float*)d_out;

    int B = in_sizes[1];
    int E = in_sizes[2] / 2;
    int N = in_sizes[0] / (B * FIN);
    int rows = B * N;

    static cudaStream_t s_side = nullptr;
    static cudaEvent_t ev_fork = nullptr, ev_join = nullptr;
    if (s_side == nullptr) {
        cudaStreamCreateWithFlags(&s_side, cudaStreamNonBlocking);
        cudaEventCreateWithFlags(&ev_fork, cudaEventDisableTiming);
        cudaEventCreateWithFlags(&ev_join, cudaEventDisableTiming);
    }

    k_init<<<(N + 255) / 256, 256>>>(N);

    // fork: graph structure (needs only edge_index) runs beside gemm1
    cudaEventRecord(ev_fork, 0);
    cudaStreamWaitEvent(s_side, ev_fork, 0);
    k_count<<<(E + 255) / 256, 256, 0, s_side>>>(ei, E);
    k_scan<<<1, 1024, 0, s_side>>>(N);
    k_csr<<<(E + 255) / 256, 256, 0, s_side>>>(ei, E);
    cudaEventRecord(ev_join, s_side);

    k_gemm1<<<(rows + 63) / 64, 128>>>(x, W1, rows, N, B);

    // join: agg1 needs both csr and gemm1 output
    cudaStreamWaitEvent(0, ev_join, 0);
    k_agg1<<<(N + 1) / 2, 256>>>(b1, N, B);
    k_gemm2<<<(rows + 63) / 64, 128>>>(W2, rows);
    k_agg2<<<(N + 1) / 2, 256>>>(b2, fcw, N, B);
    k_final<<<1, 256>>>(out, add, fcw, fcb, N, B);
}

// round 7
// speedup vs baseline: 1.7056x; 1.2303x over previous
#include <cuda_runtime.h>
#include <cuda_fp16.h>
#include <cuda_fp8.h>
#include <cstdint>

#define MAXN 20000
#define MAXE 320000
#define FIN  128
#define HID  64
#define MAXB 8

// ---------------- static device scratch (allocation-free rule) ----------------
__device__ __half g_hw[(size_t)MAXN * MAXB * HID];         // layer-1 feats, node-major, fp16
__device__ __half g_h1[(size_t)MAXN * MAXB * HID];         // layer-1 activations, fp16
__device__ unsigned char g_f8[(size_t)MAXN * MAXB * HID];  // layer-2 feats, fp8 e4m3
__device__ __half g_w1t[FIN * HID];                         // W1^T fp16 [n][k]
__device__ __half g_w2t[HID * HID];                         // W2^T fp16 [n][k]
__device__ int    g_cnt[MAXN];
__device__ int    g_offs[MAXN + 1];
__device__ int    g_cursor[MAXN];
__device__ float  g_dis[MAXN];
__device__ int    g_csr_src[MAXE];
__device__ float  g_csr_w[MAXE];
__device__ float  g_partial[MAXB * 64];

// ---------------- fp8 helpers ----------------
__device__ __forceinline__ float4 f8x4_to_f4(uint32_t p) {
    __half2_raw lo = __nv_cvt_fp8x2_to_halfraw2((__nv_fp8x2_storage_t)(p & 0xffffu), __NV_E4M3);
    __half2_raw hi = __nv_cvt_fp8x2_to_halfraw2((__nv_fp8x2_storage_t)(p >> 16), __NV_E4M3);
    float2 a = __half22float2(*(__half2*)&lo);
    float2 b = __half22float2(*(__half2*)&hi);
    return make_float4(a.x, a.y, b.x, b.y);
}
__device__ __forceinline__ unsigned short f2_to_f8x2(float a, float b) {
    return (unsigned short)__nv_cvt_float2_to_fp8x2(make_float2(a, b), __NV_SATFINITE, __NV_E4M3);
}

// ---------------- HMMA m16n8k16 fp16 -> fp32 ----------------
__device__ __forceinline__ void mma16816(float* c, uint32_t a0, uint32_t a1,
                                         uint32_t a2, uint32_t a3,
                                         uint32_t b0, uint32_t b1) {
    asm volatile(
        "mma.sync.aligned.m16n8k16.row.col.f32.f16.f16.f32 "
        "{%0,%1,%2,%3}, {%4,%5,%6,%7}, {%8,%9}, {%0,%1,%2,%3};"
        : "+f"(c[0]), "+f"(c[1]), "+f"(c[2]), "+f"(c[3])
        : "r"(a0), "r"(a1), "r"(a2), "r"(a3), "r"(b0), "r"(b1));
}

// ---------------- weight convert + transpose (once) ----------------
__global__ void k_wconv(const float* __restrict__ W1, const float* __restrict__ W2) {
    int i = blockIdx.x * blockDim.x + threadIdx.x;
    if (i < FIN * HID) {
        int k = i >> 6, n = i & 63;
        g_w1t[n * FIN + k] = __float2half_rn(W1[i]);
    } else if (i < FIN * HID + HID * HID) {
        int j = i - FIN * HID;
        int k = j >> 6, n = j & 63;
        g_w2t[n * HID + k] = __float2half_rn(W2[j]);
    }
}

// ---------------- init ----------------
__global__ void k_init(int N) {
    int i = blockIdx.x * blockDim.x + threadIdx.x;
    if (i < N) g_cnt[i] = 0;
    if (i < MAXB * 64) g_partial[i] = 0.0f;
}

// ---------------- in-degree count ----------------
__global__ void k_count(const int* __restrict__ ei, int E) {
    int e = blockIdx.x * blockDim.x + threadIdx.x;
    if (e < E) atomicAdd(&g_cnt[ei[E + e]], 1);
}

// ---------------- single-block scan ----------------
__global__ void k_scan(int N) {
    __shared__ int ss[1024];
    int tid = threadIdx.x;
    int CH = (N + 1023) >> 10;
    int base = tid * CH;
    int s = 0;
    for (int j = 0; j < CH; j++) {
        int i = base + j;
        if (i < N) s += g_cnt[i];
    }
    ss[tid] = s;
    __syncthreads();
    for (int off = 1; off < 1024; off <<= 1) {
        int v = (tid >= off) ? ss[tid - off] : 0;
        __syncthreads();
        ss[tid] += v;
        __syncthreads();
    }
    int run = (tid == 0) ? 0 : ss[tid - 1];
    for (int j = 0; j < CH; j++) {
        int i = base + j;
        if (i < N) {
            g_offs[i] = run;
            g_cursor[i] = run;
            g_dis[i] = rsqrtf(1.0f + (float)g_cnt[i]);
            run += g_cnt[i];
        }
    }
    if (tid == 0) g_offs[N] = ss[1023];
}

// ---------------- CSR fill ----------------
__global__ void k_csr(const int* __restrict__ ei, int E) {
    int e = blockIdx.x * blockDim.x + threadIdx.x;
    if (e < E) {
        int s = ei[e];
        int d = ei[E + e];
        int pos = atomicAdd(&g_cursor[d], 1);
        g_csr_src[pos] = s;
        g_csr_w[pos] = g_dis[s] * g_dis[d];
    }
}

// ---------------- GEMM1 (HMMA): g_hw = x @ W1, fp32 in -> fp16 out (node-major) ----
#define XS1 136
__global__ void __launch_bounds__(128) k_gemm1(const float* __restrict__ x,
                                               int rows, int N, int B) {
    __shared__ __align__(16) __half Xs[64 * XS1];
    __shared__ __align__(16) __half Wt[64 * XS1];
    int tid = threadIdx.x;
    size_t r0 = (size_t)blockIdx.x * 64;

    // vectorized copy of pre-transposed fp16 W1t -> smem (stride XS1)
    for (int idx = tid; idx < 64 * (FIN / 8); idx += 128) {
        int n = idx >> 4, c = idx & 15;
        *(uint4*)(Wt + n * XS1 + c * 8) = *(const uint4*)(g_w1t + n * FIN + c * 8);
    }
    for (int idx = tid; idx < 64 * (FIN / 4); idx += 128) {
        int row = idx >> 5, c = idx & 31;
        size_t r = r0 + row;
        float4 v = make_float4(0.f, 0.f, 0.f, 0.f);
        if (r < (size_t)rows) v = *(const float4*)(x + r * FIN + c * 4);
        __half2* p = (__half2*)(Xs + row * XS1 + c * 4);
        p[0] = __floats2half2_rn(v.x, v.y);
        p[1] = __floats2half2_rn(v.z, v.w);
    }
    __syncthreads();

    int wid = tid >> 5, lane = tid & 31;
    int gid = lane >> 2, tig = lane & 3;
    const __half* A0 = Xs + (wid * 16 + gid) * XS1 + 2 * tig;
    const __half* A1 = A0 + 8 * XS1;

    float acc[8][4];
#pragma unroll
    for (int i = 0; i < 8; i++)
#pragma unroll
        for (int j = 0; j < 4; j++) acc[i][j] = 0.f;

#pragma unroll
    for (int ks = 0; ks < FIN / 16; ks++) {
        int k0 = ks * 16;
        uint32_t a0 = *(const uint32_t*)(A0 + k0);
        uint32_t a1 = *(const uint32_t*)(A1 + k0);
        uint32_t a2 = *(const uint32_t*)(A0 + k0 + 8);
        uint32_t a3 = *(const uint32_t*)(A1 + k0 + 8);
#pragma unroll
        for (int nt = 0; nt < 8; nt++) {
            const __half* Bp = Wt + (nt * 8 + gid) * XS1 + k0 + 2 * tig;
            uint32_t b0 = *(const uint32_t*)(Bp);
            uint32_t b1 = *(const uint32_t*)(Bp + 8);
            mma16816(acc[nt], a0, a1, a2, a3, b0, b1);
        }
    }

    size_t r1 = r0 + wid * 16 + gid;
    size_t r2 = r1 + 8;
    if (r1 < (size_t)rows) {
        int n = (int)(r1 % N), b = (int)(r1 / N);
        __half* o = g_hw + ((size_t)n * B + b) * HID + 2 * tig;
#pragma unroll
        for (int nt = 0; nt < 8; nt++)
            *(__half2*)(o + nt * 8) = __floats2half2_rn(acc[nt][0], acc[nt][1]);
    }
    if (r2 < (size_t)rows) {
        int n = (int)(r2 % N), b = (int)(r2 / N);
        __half* o = g_hw + ((size_t)n * B + b) * HID + 2 * tig;
#pragma unroll
        for (int nt = 0; nt < 8; nt++)
            *(__half2*)(o + nt * 8) = __floats2half2_rn(acc[nt][2], acc[nt][3]);
    }
}

// ---------------- GEMM2 (HMMA): g_f8 = h1 @ W2, fp16 in -> fp8 out (node-major) ----
#define XS2 72
__global__ void __launch_bounds__(128) k_gemm2(int rows) {
    __shared__ __align__(16) __half Xs[64 * XS2];
    __shared__ __align__(16) __half Wt[64 * XS2];
    int tid = threadIdx.x;
    size_t r0 = (size_t)blockIdx.x * 64;

    for (int idx = tid; idx < 64 * (HID / 8); idx += 128) {
        int n = idx >> 3, c = idx & 7;
        *(uint4*)(Wt + n * XS2 + c * 8) = *(const uint4*)(g_w2t + n * HID + c * 8);
    }
    for (int idx = tid; idx < 64 * (HID / 8); idx += 128) {
        int row = idx >> 3, c = idx & 7;
        size_t r = r0 + row;
        uint4 v = make_uint4(0u, 0u, 0u, 0u);
        if (r < (size_t)rows) v = *(const uint4*)(g_h1 + r * HID + c * 8);
        *(uint4*)(Xs + row * XS2 + c * 8) = v;
    }
    __syncthreads();

    int wid = tid >> 5, lane = tid & 31;
    int gid = lane >> 2, tig = lane & 3;
    const __half* A0 = Xs + (wid * 16 + gid) * XS2 + 2 * tig;
    const __half* A1 = A0 + 8 * XS2;

    float acc[8][4];
#pragma unroll
    for (int i = 0; i < 8; i++)
#pragma unroll
        for (int j = 0; j < 4; j++) acc[i][j] = 0.f;

#pragma unroll
    for (int ks = 0; ks < HID / 16; ks++) {
        int k0 = ks * 16;
        uint32_t a0 = *(const uint32_t*)(A0 + k0);
        uint32_t a1 = *(const uint32_t*)(A1 + k0);
        uint32_t a2 = *(const uint32_t*)(A0 + k0 + 8);
        uint32_t a3 = *(const uint32_t*)(A1 + k0 + 8);
#pragma unroll
        for (int nt = 0; nt < 8; nt++) {
            const __half* Bp = Wt + (nt * 8 + gid) * XS2 + k0 + 2 * tig;
            uint32_t b0 = *(const uint32_t*)(Bp);
            uint32_t b1 = *(const uint32_t*)(Bp + 8);
            mma16816(acc[nt], a0, a1, a2, a3, b0, b1);
        }
    }

    size_t r1 = r0 + wid * 16 + gid;
    size_t r2 = r1 + 8;
    if (r1 < (size_t)rows) {
        unsigned char* o = g_f8 + r1 * HID + 2 * tig;
#pragma unroll
        for (int nt = 0; nt < 8; nt++)
            *(unsigned short*)(o + nt * 8) = f2_to_f8x2(acc[nt][0], acc[nt][1]);
    }
    if (r2 < (size_t)rows) {
        unsigned char* o = g_f8 + r2 * HID + 2 * tig;
#pragma unroll
        for (int nt = 0; nt < 8; nt++)
            *(unsigned short*)(o + nt * 8) = f2_to_f8x2(acc[nt][2], acc[nt][3]);
    }
}

// ---------------- layer-1 aggregation (fp16 gather) + bias + relu -> g_h1 ----------------
// 2 nodes per block; 128 threads per node, 4 halves/thread (uint2 gathers).
__global__ void __launch_bounds__(256) k_agg1(const float* __restrict__ bias,
                                              int N, int Bsz) {
    int lt = threadIdx.x & 127;
    int node = blockIdx.x * 2 + (threadIdx.x >> 7);
    if (node >= N) return;
    int f = lt * 4;
    int rowlen = Bsz * HID;
    if (f >= rowlen) return;
    int h = f & (HID - 1);
    float d = g_dis[node];
    float sn = d * d;
    size_t base = (size_t)node * rowlen;

    float4 bz = make_float4(bias[h], bias[h + 1], bias[h + 2], bias[h + 3]);
    uint2 sv = *(const uint2*)(g_hw + base + f);
    float2 v0 = __half22float2(*(__half2*)&sv.x);
    float2 v1 = __half22float2(*(__half2*)&sv.y);
    float4 acc = make_float4(fmaf(v0.x, sn, bz.x), fmaf(v0.y, sn, bz.y),
                             fmaf(v1.x, sn, bz.z), fmaf(v1.y, sn, bz.w));

    int e = g_offs[node], e1 = g_offs[node + 1];
    for (; e + 3 < e1; e += 4) {
        int s0 = g_csr_src[e], s1 = g_csr_src[e + 1];
        int s2 = g_csr_src[e + 2], s3 = g_csr_src[e + 3];
        float w0 = g_csr_w[e], w1 = g_csr_w[e + 1];
        float w2 = g_csr_w[e + 2], w3 = g_csr_w[e + 3];
        uint2 p0 = *(const uint2*)(g_hw + (size_t)s0 * rowlen + f);
        uint2 p1 = *(const uint2*)(g_hw + (size_t)s1 * rowlen + f);
        uint2 p2 = *(const uint2*)(g_hw + (size_t)s2 * rowlen + f);
        uint2 p3 = *(const uint2*)(g_hw + (size_t)s3 * rowlen + f);
        float2 a, b;
        a = __half22float2(*(__half2*)&p0.x); b = __half22float2(*(__half2*)&p0.y);
        acc.x = fmaf(w0, a.x, acc.x); acc.y = fmaf(w0, a.y, acc.y);
        acc.z = fmaf(w0, b.x, acc.z); acc.w = fmaf(w0, b.y, acc.w);
        a = __half22float2(*(__half2*)&p1.x); b = __half22float2(*(__half2*)&p1.y);
        acc.x = fmaf(w1, a.x, acc.x); acc.y = fmaf(w1, a.y, acc.y);
        acc.z = fmaf(w1, b.x, acc.z); acc.w = fmaf(w1, b.y, acc.w);
        a = __half22float2(*(__half2*)&p2.x); b = __half22float2(*(__half2*)&p2.y);
        acc.x = fmaf(w2, a.x, acc.x); acc.y = fmaf(w2, a.y, acc.y);
        acc.z = fmaf(w2, b.x, acc.z); acc.w = fmaf(w2, b.y, acc.w);
        a = __half22float2(*(__half2*)&p3.x); b = __half22float2(*(__half2*)&p3.y);
        acc.x = fmaf(w3, a.x, acc.x); acc.y = fmaf(w3, a.y, acc.y);
        acc.z = fmaf(w3, b.x, acc.z); acc.w = fmaf(w3, b.y, acc.w);
    }
    for (; e < e1; e++) {
        int s0 = g_csr_src[e];
        float w0 = g_csr_w[e];
        uint2 p0 = *(const uint2*)(g_hw + (size_t)s0 * rowlen + f);
        float2 a = __half22float2(*(__half2*)&p0.x);
        float2 b = __half22float2(*(__half2*)&p0.y);
        acc.x = fmaf(w0, a.x, acc.x); acc.y = fmaf(w0, a.y, acc.y);
        acc.z = fmaf(w0, b.x, acc.z); acc.w = fmaf(w0, b.y, acc.w);
    }
    __half2 o0 = __floats2half2_rn(fmaxf(acc.x, 0.f), fmaxf(acc.y, 0.f));
    __half2 o1 = __floats2half2_rn(fmaxf(acc.z, 0.f), fmaxf(acc.w, 0.f));
    uint2 st;
    st.x = *(unsigned int*)&o0;
    st.y = *(unsigned int*)&o1;
    *(uint2*)(g_h1 + base + f) = st;
}

// ---------------- layer-2 aggregation (fp8 gather) + relu, fused fc dot + pool ----------------
__global__ void __launch_bounds__(256) k_agg2(const float* __restrict__ bias,
                                              const float* __restrict__ fcw,
                                              int N, int Bsz) {
    int lt = threadIdx.x & 127;
    int node = blockIdx.x * 2 + (threadIdx.x >> 7);
    if (node >= N) return;
    int f = lt * 4;
    int rowlen = Bsz * HID;
    if (f >= rowlen) return;
    int h = f & (HID - 1);
    float d = g_dis[node];
    float sn = d * d;
    size_t base = (size_t)node * rowlen;

    float4 bz = make_float4(bias[h], bias[h + 1], bias[h + 2], bias[h + 3]);
    float4 v = f8x4_to_f4(*(const uint32_t*)(g_f8 + base + f));
    float4 acc = make_float4(fmaf(v.x, sn, bz.x), fmaf(v.y, sn, bz.y),
                             fmaf(v.z, sn, bz.z), fmaf(v.w, sn, bz.w));

    int e = g_offs[node], e1 = g_offs[node + 1];
    for (; e + 3 < e1; e += 4) {
        int s0 = g_csr_src[e], s1 = g_csr_src[e + 1];
        int s2 = g_csr_src[e + 2], s3 = g_csr_src[e + 3];
        float w0 = g_csr_w[e], w1 = g_csr_w[e + 1];
        float w2 = g_csr_w[e + 2], w3 = g_csr_w[e + 3];
        float4 m0 = f8x4_to_f4(*(const uint32_t*)(g_f8 + (size_t)s0 * rowlen + f));
        float4 m1 = f8x4_to_f4(*(const uint32_t*)(g_f8 + (size_t)s1 * rowlen + f));
        float4 m2 = f8x4_to_f4(*(const uint32_t*)(g_f8 + (size_t)s2 * rowlen + f));
        float4 m3 = f8x4_to_f4(*(const uint32_t*)(g_f8 + (size_t)s3 * rowlen + f));
        acc.x = fmaf(w0, m0.x, acc.x); acc.y = fmaf(w0, m0.y, acc.y);
        acc.z = fmaf(w0, m0.z, acc.z); acc.w = fmaf(w0, m0.w, acc.w);
        acc.x = fmaf(w1, m1.x, acc.x); acc.y = fmaf(w1, m1.y, acc.y);
        acc.z = fmaf(w1, m1.z, acc.z); acc.w = fmaf(w1, m1.w, acc.w);
        acc.x = fmaf(w2, m2.x, acc.x); acc.y = fmaf(w2, m2.y, acc.y);
        acc.z = fmaf(w2, m2.z, acc.z); acc.w = fmaf(w2, m2.w, acc.w);
        acc.x = fmaf(w3, m3.x, acc.x); acc.y = fmaf(w3, m3.y, acc.y);
        acc.z = fmaf(w3, m3.z, acc.z); acc.w = fmaf(w3, m3.w, acc.w);
    }
    for (; e < e1; e++) {
        int s0 = g_csr_src[e];
        float w0 = g_csr_w[e];
        float4 m0 = f8x4_to_f4(*(const uint32_t*)(g_f8 + (size_t)s0 * rowlen + f));
        acc.x = fmaf(w0, m0.x, acc.x); acc.y = fmaf(w0, m0.y, acc.y);
        acc.z = fmaf(w0, m0.z, acc.z); acc.w = fmaf(w0, m0.w, acc.w);
    }

    float c = fmaxf(acc.x, 0.f) * fcw[h] + fmaxf(acc.y, 0.f) * fcw[h + 1] +
              fmaxf(acc.z, 0.f) * fcw[h + 2] + fmaxf(acc.w, 0.f) * fcw[h + 3];
#pragma unroll
    for (int o = 8; o; o >>= 1) c += __shfl_xor_sync(0xffffffffu, c, o);
    if ((threadIdx.x & 15) == 0) {
        int b = lt >> 4;
        atomicAdd(&g_partial[b * 64 + (node & 63)], c);
    }
}

// ---------------- final reduce ----------------
__global__ void k_final(float* __restrict__ out, const float* __restrict__ add,
                        const float* __restrict__ fcw, const float* __restrict__ fcb,
                        int N, int Bsz) {
    int b = threadIdx.x >> 5;
    int lane = threadIdx.x & 31;
    if (b < Bsz) {
        float s = g_partial[b * 64 + lane] + g_partial[b * 64 + 32 + lane];
#pragma unroll
        for (int o = 16; o; o >>= 1) s += __shfl_xor_sync(0xffffffffu, s, o);
        if (lane == 0)
            out[b] = s * (1.0f / (float)N) + add[b] * fcw[HID] + fcb[0];
    }
}

// ---------------- launch ----------------
extern "C" void kernel_launch(void* const* d_in, const int* in_sizes, int n_in,
                              void* d_out, int out_size) {
    const float* x   = (const float*)d_in[0];
    const float* add = (const float*)d_in[1];
    const int*   ei  = (const int*)d_in[2];
    const float* W1  = (const float*)d_in[3];
    const float* b1  = (const float*)d_in[4];
    const float* W2  = (const float*)d_in[5];
    const float* b2  = (const float*)d_in[6];
    const float* fcw = (const float*)d_in[7];
    const float* fcb = (const float*)d_in[8];
    float* out = (float*)d_out;

    int B = in_sizes[1];
    int E = in_sizes[2] / 2;
    int N = in_sizes[0] / (B * FIN);
    int rows = B * N;

    static cudaStream_t s_side = nullptr;
    static cudaEvent_t ev_fork = nullptr, ev_join = nullptr;
    if (s_side == nullptr) {
        cudaStreamCreateWithFlags(&s_side, cudaStreamNonBlocking);
        cudaEventCreateWithFlags(&ev_fork, cudaEventDisableTiming);
        cudaEventCreateWithFlags(&ev_join, cudaEventDisableTiming);
    }

    // fork: init + graph structure (needs only edge_index) beside wconv+gemm1
    cudaEventRecord(ev_fork, 0);
    cudaStreamWaitEvent(s_side, ev_fork, 0);
    k_init<<<(N + 255) / 256, 256, 0, s_side>>>(N);
    k_count<<<(E + 255) / 256, 256, 0, s_side>>>(ei, E);
    k_scan<<<1, 1024, 0, s_side>>>(N);
    k_csr<<<(E + 255) / 256, 256, 0, s_side>>>(ei, E);
    cudaEventRecord(ev_join, s_side);

    k_wconv<<<(FIN * HID + HID * HID + 255) / 256, 256>>>(W1, W2);
    k_gemm1<<<(rows + 63) / 64, 128>>>(x, rows, N, B);

    // join: agg1 needs both csr and gemm1 output
    cudaStreamWaitEvent(0, ev_join, 0);
    k_agg1<<<(N + 1) / 2, 256>>>(b1, N, B);
    k_gemm2<<<(rows + 63) / 64, 128>>>(rows);
    k_agg2<<<(N + 1) / 2, 256>>>(b2, fcw, N, B);
    k_final<<<1, 256>>>(out, add, fcw, fcb, N, B);
}

// round 9
// speedup vs baseline: 1.7335x; 1.0164x over previous
#include <cuda_runtime.h>
#include <cuda_fp16.h>
#include <cuda_fp8.h>
#include <cstdint>

#define MAXN 20000
#define MAXE 320000
#define FIN  128
#define HID  64
#define MAXB 8

// ---------------- static device scratch (allocation-free rule) ----------------
__device__ __half g_hw[(size_t)MAXN * MAXB * HID];         // layer-1 feats, node-major, fp16
__device__ __half g_h1[(size_t)MAXN * MAXB * HID];         // layer-1 activations, fp16
__device__ unsigned char g_f8[(size_t)MAXN * MAXB * HID];  // layer-2 feats, fp8 e4m3
__device__ __half g_w1t[FIN * HID];                         // W1^T fp16 [n][k]
__device__ __half g_w2t[HID * HID];                         // W2^T fp16 [n][k]
__device__ int    g_cnt[MAXN];
__device__ int    g_offs[MAXN + 1];
__device__ int    g_cursor[MAXN];
__device__ float  g_dis[MAXN];
__device__ int    g_csr_src[MAXE];
__device__ float  g_csr_w[MAXE];
__device__ float  g_partial[MAXB * 64];

// ---------------- fp8 helpers ----------------
__device__ __forceinline__ float4 f8x4_to_f4(uint32_t p) {
    __half2_raw lo = __nv_cvt_fp8x2_to_halfraw2((__nv_fp8x2_storage_t)(p & 0xffffu), __NV_E4M3);
    __half2_raw hi = __nv_cvt_fp8x2_to_halfraw2((__nv_fp8x2_storage_t)(p >> 16), __NV_E4M3);
    float2 a = __half22float2(*(__half2*)&lo);
    float2 b = __half22float2(*(__half2*)&hi);
    return make_float4(a.x, a.y, b.x, b.y);
}
__device__ __forceinline__ unsigned short f2_to_f8x2(float a, float b) {
    return (unsigned short)__nv_cvt_float2_to_fp8x2(make_float2(a, b), __NV_SATFINITE, __NV_E4M3);
}

// ---------------- HMMA m16n8k16 fp16 -> fp32 ----------------
__device__ __forceinline__ void mma16816(float* c, uint32_t a0, uint32_t a1,
                                         uint32_t a2, uint32_t a3,
                                         uint32_t b0, uint32_t b1) {
    asm volatile(
        "mma.sync.aligned.m16n8k16.row.col.f32.f16.f16.f32 "
        "{%0,%1,%2,%3}, {%4,%5,%6,%7}, {%8,%9}, {%0,%1,%2,%3};"
        : "+f"(c[0]), "+f"(c[1]), "+f"(c[2]), "+f"(c[3])
        : "r"(a0), "r"(a1), "r"(a2), "r"(a3), "r"(b0), "r"(b1));
}

// ---------------- weight convert + transpose (once) ----------------
__global__ void k_wconv(const float* __restrict__ W1, const float* __restrict__ W2) {
    int i = blockIdx.x * blockDim.x + threadIdx.x;
    if (i < FIN * HID) {
        int k = i >> 6, n = i & 63;
        g_w1t[n * FIN + k] = __float2half_rn(W1[i]);
    } else if (i < FIN * HID + HID * HID) {
        int j = i - FIN * HID;
        int k = j >> 6, n = j & 63;
        g_w2t[n * HID + k] = __float2half_rn(W2[j]);
    }
}

// ---------------- init ----------------
__global__ void k_init(int N) {
    int i = blockIdx.x * blockDim.x + threadIdx.x;
    if (i < N) g_cnt[i] = 0;
    if (i < MAXB * 64) g_partial[i] = 0.0f;
}

// ---------------- in-degree count ----------------
__global__ void k_count(const int* __restrict__ ei, int E) {
    int e = blockIdx.x * blockDim.x + threadIdx.x;
    if (e < E) atomicAdd(&g_cnt[ei[E + e]], 1);
}

// ---------------- single-block scan ----------------
__global__ void k_scan(int N) {
    __shared__ int ss[1024];
    int tid = threadIdx.x;
    int CH = (N + 1023) >> 10;
    int base = tid * CH;
    int s = 0;
    for (int j = 0; j < CH; j++) {
        int i = base + j;
        if (i < N) s += g_cnt[i];
    }
    ss[tid] = s;
    __syncthreads();
    for (int off = 1; off < 1024; off <<= 1) {
        int v = (tid >= off) ? ss[tid - off] : 0;
        __syncthreads();
        ss[tid] += v;
        __syncthreads();
    }
    int run = (tid == 0) ? 0 : ss[tid - 1];
    for (int j = 0; j < CH; j++) {
        int i = base + j;
        if (i < N) {
            g_offs[i] = run;
            g_cursor[i] = run;
            g_dis[i] = rsqrtf(1.0f + (float)g_cnt[i]);
            run += g_cnt[i];
        }
    }
    if (tid == 0) g_offs[N] = ss[1023];
}

// ---------------- CSR fill ----------------
__global__ void k_csr(const int* __restrict__ ei, int E) {
    int e = blockIdx.x * blockDim.x + threadIdx.x;
    if (e < E) {
        int s = ei[e];
        int d = ei[E + e];
        int pos = atomicAdd(&g_cursor[d], 1);
        g_csr_src[pos] = s;
        g_csr_w[pos] = g_dis[s] * g_dis[d];
    }
}

// ---------------- GEMM1 (HMMA): g_hw = x @ W1, fp32 in -> fp16 out (node-major) ----
// Epilogue staged through smem for coalesced 128B row writes.
#define XS1 136
#define CS1 72   // stage stride in halves (144B, 16B-aligned rows)
__global__ void __launch_bounds__(128) k_gemm1(const float* __restrict__ x,
                                               int rows, int N, int B) {
    __shared__ __align__(16) __half Xs[64 * XS1];
    __shared__ __align__(16) __half Wt[64 * XS1];
    __shared__ __align__(16) __half Cs[64 * CS1];
    int tid = threadIdx.x;
    size_t r0 = (size_t)blockIdx.x * 64;

    for (int idx = tid; idx < 64 * (FIN / 8); idx += 128) {
        int n = idx >> 4, c = idx & 15;
        *(uint4*)(Wt + n * XS1 + c * 8) = *(const uint4*)(g_w1t + n * FIN + c * 8);
    }
    for (int idx = tid; idx < 64 * (FIN / 4); idx += 128) {
        int row = idx >> 5, c = idx & 31;
        size_t r = r0 + row;
        float4 v = make_float4(0.f, 0.f, 0.f, 0.f);
        if (r < (size_t)rows) v = *(const float4*)(x + r * FIN + c * 4);
        __half2* p = (__half2*)(Xs + row * XS1 + c * 4);
        p[0] = __floats2half2_rn(v.x, v.y);
        p[1] = __floats2half2_rn(v.z, v.w);
    }
    __syncthreads();

    int wid = tid >> 5, lane = tid & 31;
    int gid = lane >> 2, tig = lane & 3;
    const __half* A0 = Xs + (wid * 16 + gid) * XS1 + 2 * tig;
    const __half* A1 = A0 + 8 * XS1;

    float acc[8][4];
#pragma unroll
    for (int i = 0; i < 8; i++)
#pragma unroll
        for (int j = 0; j < 4; j++) acc[i][j] = 0.f;

#pragma unroll
    for (int ks = 0; ks < FIN / 16; ks++) {
        int k0 = ks * 16;
        uint32_t a0 = *(const uint32_t*)(A0 + k0);
        uint32_t a1 = *(const uint32_t*)(A1 + k0);
        uint32_t a2 = *(const uint32_t*)(A0 + k0 + 8);
        uint32_t a3 = *(const uint32_t*)(A1 + k0 + 8);
#pragma unroll
        for (int nt = 0; nt < 8; nt++) {
            const __half* Bp = Wt + (nt * 8 + gid) * XS1 + k0 + 2 * tig;
            uint32_t b0 = *(const uint32_t*)(Bp);
            uint32_t b1 = *(const uint32_t*)(Bp + 8);
            mma16816(acc[nt], a0, a1, a2, a3, b0, b1);
        }
    }

    // stage results in smem, then coalesced row writes
    __syncthreads();
    {
        int row1 = wid * 16 + gid, row2 = row1 + 8;
#pragma unroll
        for (int nt = 0; nt < 8; nt++) {
            *(__half2*)(Cs + row1 * CS1 + nt * 8 + 2 * tig) =
                __floats2half2_rn(acc[nt][0], acc[nt][1]);
            *(__half2*)(Cs + row2 * CS1 + nt * 8 + 2 * tig) =
                __floats2half2_rn(acc[nt][2], acc[nt][3]);
        }
    }
    __syncthreads();
    // 64 rows x 128B; each row = 8 uint4. 128 threads -> 16 rows/pass.
    for (int idx = tid; idx < 64 * 8; idx += 128) {
        int row = idx >> 3, c = idx & 7;
        size_t r = r0 + row;
        if (r < (size_t)rows) {
            int n = (int)(r % N), b = (int)(r / N);
            *(uint4*)(g_hw + ((size_t)n * B + b) * HID + c * 8) =
                *(const uint4*)(Cs + row * CS1 + c * 8);
        }
    }
}

// ---------------- GEMM2 (HMMA): g_f8 = h1 @ W2, fp16 in -> fp8 out (node-major) ----
#define XS2 72
#define CS2 80   // fp8 stage stride in BYTES; 80 % 16 == 0 -> aligned uint4 rows
__global__ void __launch_bounds__(128) k_gemm2(int rows) {
    __shared__ __align__(16) __half Xs[64 * XS2];
    __shared__ __align__(16) __half Wt[64 * XS2];
    __shared__ __align__(16) unsigned char Cs[64 * CS2];
    int tid = threadIdx.x;
    size_t r0 = (size_t)blockIdx.x * 64;

    for (int idx = tid; idx < 64 * (HID / 8); idx += 128) {
        int n = idx >> 3, c = idx & 7;
        *(uint4*)(Wt + n * XS2 + c * 8) = *(const uint4*)(g_w2t + n * HID + c * 8);
    }
    for (int idx = tid; idx < 64 * (HID / 8); idx += 128) {
        int row = idx >> 3, c = idx & 7;
        size_t r = r0 + row;
        uint4 v = make_uint4(0u, 0u, 0u, 0u);
        if (r < (size_t)rows) v = *(const uint4*)(g_h1 + r * HID + c * 8);
        *(uint4*)(Xs + row * XS2 + c * 8) = v;
    }
    __syncthreads();

    int wid = tid >> 5, lane = tid & 31;
    int gid = lane >> 2, tig = lane & 3;
    const __half* A0 = Xs + (wid * 16 + gid) * XS2 + 2 * tig;
    const __half* A1 = A0 + 8 * XS2;

    float acc[8][4];
#pragma unroll
    for (int i = 0; i < 8; i++)
#pragma unroll
        for (int j = 0; j < 4; j++) acc[i][j] = 0.f;

#pragma unroll
    for (int ks = 0; ks < HID / 16; ks++) {
        int k0 = ks * 16;
        uint32_t a0 = *(const uint32_t*)(A0 + k0);
        uint32_t a1 = *(const uint32_t*)(A1 + k0);
        uint32_t a2 = *(const uint32_t*)(A0 + k0 + 8);
        uint32_t a3 = *(const uint32_t*)(A1 + k0 + 8);
#pragma unroll
        for (int nt = 0; nt < 8; nt++) {
            const __half* Bp = Wt + (nt * 8 + gid) * XS2 + k0 + 2 * tig;
            uint32_t b0 = *(const uint32_t*)(Bp);
            uint32_t b1 = *(const uint32_t*)(Bp + 8);
            mma16816(acc[nt], a0, a1, a2, a3, b0, b1);
        }
    }

    __syncthreads();
    {
        int row1 = wid * 16 + gid, row2 = row1 + 8;
#pragma unroll
        for (int nt = 0; nt < 8; nt++) {
            *(unsigned short*)(Cs + row1 * CS2 + nt * 8 + 2 * tig) =
                f2_to_f8x2(acc[nt][0], acc[nt][1]);
            *(unsigned short*)(Cs + row2 * CS2 + nt * 8 + 2 * tig) =
                f2_to_f8x2(acc[nt][2], acc[nt][3]);
        }
    }
    __syncthreads();
    // 64 rows x 64B; each row = 4 uint4. 128 threads -> 32 rows/pass.
    for (int idx = tid; idx < 64 * 4; idx += 128) {
        int row = idx >> 2, c = idx & 3;
        size_t r = r0 + row;
        if (r < (size_t)rows)
            *(uint4*)(g_f8 + r * HID + c * 16) = *(const uint4*)(Cs + row * CS2 + c * 16);
    }
}

// ---------------- layer-1 aggregation (fp16 gather, 16B/thread) -> g_h1 ----------------
// 4 nodes per block; 64 threads per node, 8 halves/thread (uint4 gathers).
__global__ void __launch_bounds__(256) k_agg1(const float* __restrict__ bias,
                                              int N, int Bsz) {
    int lt = threadIdx.x & 63;
    int node = blockIdx.x * 4 + (threadIdx.x >> 6);
    if (node >= N) return;
    int f = lt * 8;
    int rowlen = Bsz * HID;
    if (f >= rowlen) return;
    int h = f & (HID - 1);
    float d = g_dis[node];
    float sn = d * d;
    size_t base = (size_t)node * rowlen;

    float acc[8];
    {
        uint4 sv = *(const uint4*)(g_hw + base + f);
        const __half2* hp = (const __half2*)&sv;
#pragma unroll
        for (int j = 0; j < 4; j++) {
            float2 a = __half22float2(hp[j]);
            acc[j * 2]     = fmaf(a.x, sn, bias[h + j * 2]);
            acc[j * 2 + 1] = fmaf(a.y, sn, bias[h + j * 2 + 1]);
        }
    }

    int e = g_offs[node], e1 = g_offs[node + 1];
    for (; e + 3 < e1; e += 4) {
        int s0 = g_csr_src[e], s1 = g_csr_src[e + 1];
        int s2 = g_csr_src[e + 2], s3 = g_csr_src[e + 3];
        float w0 = g_csr_w[e], w1 = g_csr_w[e + 1];
        float w2 = g_csr_w[e + 2], w3 = g_csr_w[e + 3];
        uint4 p0 = *(const uint4*)(g_hw + (size_t)s0 * rowlen + f);
        uint4 p1 = *(const uint4*)(g_hw + (size_t)s1 * rowlen + f);
        uint4 p2 = *(const uint4*)(g_hw + (size_t)s2 * rowlen + f);
        uint4 p3 = *(const uint4*)(g_hw + (size_t)s3 * rowlen + f);
        const __half2* q0 = (const __half2*)&p0;
        const __half2* q1 = (const __half2*)&p1;
        const __half2* q2 = (const __half2*)&p2;
        const __half2* q3 = (const __half2*)&p3;
#pragma unroll
        for (int j = 0; j < 4; j++) {
            float2 a;
            a = __half22float2(q0[j]);
            acc[j * 2] = fmaf(w0, a.x, acc[j * 2]); acc[j * 2 + 1] = fmaf(w0, a.y, acc[j * 2 + 1]);
            a = __half22float2(q1[j]);
            acc[j * 2] = fmaf(w1, a.x, acc[j * 2]); acc[j * 2 + 1] = fmaf(w1, a.y, acc[j * 2 + 1]);
            a = __half22float2(q2[j]);
            acc[j * 2] = fmaf(w2, a.x, acc[j * 2]); acc[j * 2 + 1] = fmaf(w2, a.y, acc[j * 2 + 1]);
            a = __half22float2(q3[j]);
            acc[j * 2] = fmaf(w3, a.x, acc[j * 2]); acc[j * 2 + 1] = fmaf(w3, a.y, acc[j * 2 + 1]);
        }
    }
    for (; e < e1; e++) {
        int s0 = g_csr_src[e];
        float w0 = g_csr_w[e];
        uint4 p0 = *(const uint4*)(g_hw + (size_t)s0 * rowlen + f);
        const __half2* q0 = (const __half2*)&p0;
#pragma unroll
        for (int j = 0; j < 4; j++) {
            float2 a = __half22float2(q0[j]);
            acc[j * 2] = fmaf(w0, a.x, acc[j * 2]); acc[j * 2 + 1] = fmaf(w0, a.y, acc[j * 2 + 1]);
        }
    }
    uint4 st;
    __half2* so = (__half2*)&st;
#pragma unroll
    for (int j = 0; j < 4; j++)
        so[j] = __floats2half2_rn(fmaxf(acc[j * 2], 0.f), fmaxf(acc[j * 2 + 1], 0.f));
    *(uint4*)(g_h1 + base + f) = st;
}

// ---------------- layer-2 aggregation (fp8 gather, 8B/thread) + fc dot + pool ----------------
__global__ void __launch_bounds__(256) k_agg2(const float* __restrict__ bias,
                                              const float* __restrict__ fcw,
                                              int N, int Bsz) {
    int lt = threadIdx.x & 63;
    int node = blockIdx.x * 4 + (threadIdx.x >> 6);
    if (node >= N) return;
    int f = lt * 8;
    int rowlen = Bsz * HID;
    if (f >= rowlen) return;
    int h = f & (HID - 1);
    float d = g_dis[node];
    float sn = d * d;
    size_t base = (size_t)node * rowlen;

    float acc[8];
    {
        uint2 sv = *(const uint2*)(g_f8 + base + f);
        float4 a = f8x4_to_f4(sv.x), b = f8x4_to_f4(sv.y);
        acc[0] = fmaf(a.x, sn, bias[h]);     acc[1] = fmaf(a.y, sn, bias[h + 1]);
        acc[2] = fmaf(a.z, sn, bias[h + 2]); acc[3] = fmaf(a.w, sn, bias[h + 3]);
        acc[4] = fmaf(b.x, sn, bias[h + 4]); acc[5] = fmaf(b.y, sn, bias[h + 5]);
        acc[6] = fmaf(b.z, sn, bias[h + 6]); acc[7] = fmaf(b.w, sn, bias[h + 7]);
    }

    int e = g_offs[node], e1 = g_offs[node + 1];
    for (; e + 3 < e1; e += 4) {
        int s0 = g_csr_src[e], s1 = g_csr_src[e + 1];
        int s2 = g_csr_src[e + 2], s3 = g_csr_src[e + 3];
        float w0 = g_csr_w[e], w1 = g_csr_w[e + 1];
        float w2 = g_csr_w[e + 2], w3 = g_csr_w[e + 3];
        uint2 p0 = *(const uint2*)(g_f8 + (size_t)s0 * rowlen + f);
        uint2 p1 = *(const uint2*)(g_f8 + (size_t)s1 * rowlen + f);
        uint2 p2 = *(const uint2*)(g_f8 + (size_t)s2 * rowlen + f);
        uint2 p3 = *(const uint2*)(g_f8 + (size_t)s3 * rowlen + f);
#pragma unroll
        for (int j = 0; j < 2; j++) {
            uint32_t u0 = j ? p0.y : p0.x, u1 = j ? p1.y : p1.x;
            uint32_t u2 = j ? p2.y : p2.x, u3 = j ? p3.y : p3.x;
            float4 m;
            m = f8x4_to_f4(u0);
            acc[j*4+0] = fmaf(w0, m.x, acc[j*4+0]); acc[j*4+1] = fmaf(w0, m.y, acc[j*4+1]);
            acc[j*4+2] = fmaf(w0, m.z, acc[j*4+2]); acc[j*4+3] = fmaf(w0, m.w, acc[j*4+3]);
            m = f8x4_to_f4(u1);
            acc[j*4+0] = fmaf(w1, m.x, acc[j*4+0]); acc[j*4+1] = fmaf(w1, m.y, acc[j*4+1]);
            acc[j*4+2] = fmaf(w1, m.z, acc[j*4+2]); acc[j*4+3] = fmaf(w1, m.w, acc[j*4+3]);
            m = f8x4_to_f4(u2);
            acc[j*4+0] = fmaf(w2, m.x, acc[j*4+0]); acc[j*4+1] = fmaf(w2, m.y, acc[j*4+1]);
            acc[j*4+2] = fmaf(w2, m.z, acc[j*4+2]); acc[j*4+3] = fmaf(w2, m.w, acc[j*4+3]);
            m = f8x4_to_f4(u3);
            acc[j*4+0] = fmaf(w3, m.x, acc[j*4+0]); acc[j*4+1] = fmaf(w3, m.y, acc[j*4+1]);
            acc[j*4+2] = fmaf(w3, m.z, acc[j*4+2]); acc[j*4+3] = fmaf(w3, m.w, acc[j*4+3]);
        }
    }
    for (; e < e1; e++) {
        int s0 = g_csr_src[e];
        float w0 = g_csr_w[e];
        uint2 p0 = *(const uint2*)(g_f8 + (size_t)s0 * rowlen + f);
#pragma unroll
        for (int j = 0; j < 2; j++) {
            float4 m = f8x4_to_f4(j ? p0.y : p0.x);
            acc[j*4+0] = fmaf(w0, m.x, acc[j*4+0]); acc[j*4+1] = fmaf(w0, m.y, acc[j*4+1]);
            acc[j*4+2] = fmaf(w0, m.z, acc[j*4+2]); acc[j*4+3] = fmaf(w0, m.w, acc[j*4+3]);
        }
    }

    float c = 0.f;
#pragma unroll
    for (int j = 0; j < 8; j++) c = fmaf(fmaxf(acc[j], 0.f), fcw[h + j], c);
    // reduce within 8-lane groups (one batch per group)
#pragma unroll
    for (int o = 4; o; o >>= 1) c += __shfl_xor_sync(0xffffffffu, c, o);
    if ((threadIdx.x & 7) == 0) {
        int b = lt >> 3;
        atomicAdd(&g_partial[b * 64 + (node & 63)], c);
    }
}

// ---------------- final reduce ----------------
__global__ void k_final(float* __restrict__ out, const float* __restrict__ add,
                        const float* __restrict__ fcw, const float* __restrict__ fcb,
                        int N, int Bsz) {
    int b = threadIdx.x >> 5;
    int lane = threadIdx.x & 31;
    if (b < Bsz) {
        float s = g_partial[b * 64 + lane] + g_partial[b * 64 + 32 + lane];
#pragma unroll
        for (int o = 16; o; o >>= 1) s += __shfl_xor_sync(0xffffffffu, s, o);
        if (lane == 0)
            out[b] = s * (1.0f / (float)N) + add[b] * fcw[HID] + fcb[0];
    }
}

// ---------------- launch ----------------
extern "C" void kernel_launch(void* const* d_in, const int* in_sizes, int n_in,
                              void* d_out, int out_size) {
    const float* x   = (const float*)d_in[0];
    const float* add = (const float*)d_in[1];
    const int*   ei  = (const int*)d_in[2];
    const float* W1  = (const float*)d_in[3];
    const float* b1  = (const float*)d_in[4];
    const float* W2  = (const float*)d_in[5];
    const float* b2  = (const float*)d_in[6];
    const float* fcw = (const float*)d_in[7];
    const float* fcb = (const float*)d_in[8];
    float* out = (float*)d_out;

    int B = in_sizes[1];
    int E = in_sizes[2] / 2;
    int N = in_sizes[0] / (B * FIN);
    int rows = B * N;

    static cudaStream_t s_side = nullptr;
    static cudaEvent_t ev_fork = nullptr, ev_join = nullptr;
    if (s_side == nullptr) {
        cudaStreamCreateWithFlags(&s_side, cudaStreamNonBlocking);
        cudaEventCreateWithFlags(&ev_fork, cudaEventDisableTiming);
        cudaEventCreateWithFlags(&ev_join, cudaEventDisableTiming);
    }

    // fork: init + graph structure (needs only edge_index) beside wconv+gemm1
    cudaEventRecord(ev_fork, 0);
    cudaStreamWaitEvent(s_side, ev_fork, 0);
    k_init<<<(N + 255) / 256, 256, 0, s_side>>>(N);
    k_count<<<(E + 255) / 256, 256, 0, s_side>>>(ei, E);
    k_scan<<<1, 1024, 0, s_side>>>(N);
    k_csr<<<(E + 255) / 256, 256, 0, s_side>>>(ei, E);
    cudaEventRecord(ev_join, s_side);

    k_wconv<<<(FIN * HID + HID * HID + 255) / 256, 256>>>(W1, W2);
    k_gemm1<<<(rows + 63) / 64, 128>>>(x, rows, N, B);

    // join: agg1 needs both csr and gemm1 output
    cudaStreamWaitEvent(0, ev_join, 0);
    k_agg1<<<(N + 3) / 4, 256>>>(b1, N, B);
    k_gemm2<<<(rows + 63) / 64, 128>>>(rows);
    k_agg2<<<(N + 3) / 4, 256>>>(b2, fcw, N, B);
    k_final<<<1, 256>>>(out, add, fcw, fcb, N, B);
}